// round 1
// baseline (speedup 1.0000x reference)
#include <cuda_runtime.h>

// ---------------------------------------------------------------------------
// Problem constants
// ---------------------------------------------------------------------------
static constexpr int B_  = 8;
static constexpr int S_  = 1024;
static constexpr int D_  = 1024;
static constexpr int H_  = 16;
static constexpr int DK_ = 64;
static constexpr int V_  = 65;            // 2*MAXREL+1
static constexpr int BH_ = B_ * H_;       // 128
static constexpr int MROWS = B_ * S_;     // 8192
static constexpr int NROW  = BH_ * S_;    // 131072 (b,h,s) rows
static constexpr size_t SCORES_ELEMS = (size_t)BH_ * S_ * S_;  // 134217728
static constexpr int FINAL_ELEMS = MROWS * D_;                 // 8388608

// ---------------------------------------------------------------------------
// Device scratch (static — no allocation allowed)
// ---------------------------------------------------------------------------
__device__ float g_qp[BH_ * S_ * DK_];     // Q projection, [bh][s][d], pre-scaled 1/8
__device__ float g_kp[BH_ * S_ * DK_];
__device__ float g_vp[BH_ * S_ * DK_];
__device__ float g_qrel[NROW * V_];        // q . rel_k[t]
__device__ float g_w[NROW * V_];           // relative-value buckets
__device__ float g_scores[SCORES_ELEMS];   // scores, then attn in-place
__device__ float g_ctx[MROWS * D_];        // [b][s][h*64+d]
__device__ unsigned g_flags;
__device__ int g_mask_mode;

// ---------------------------------------------------------------------------
// Mask dtype detection (bool serialization is ambiguous: f32/u8/i32/bf16)
// ---------------------------------------------------------------------------
__global__ void k_reset_flags() { g_flags = 0u; }

__global__ void k_detect_mask(const unsigned* __restrict__ w, int n) {
    unsigned f = 0;
    for (int i = blockIdx.x * blockDim.x + threadIdx.x; i < n;
         i += gridDim.x * blockDim.x) {
        unsigned x = w[i];
        if (x == 0u) continue;
        if (x == 0x3F800000u) { f |= 1u; continue; }            // fp32 1.0
        if ((x & ~0x01010101u) == 0u) {                         // bytes in {0,1}
            f |= (x == 1u) ? 16u : 2u;                          // x==1 ambiguous (int32)
            continue;
        }
        unsigned lo = x & 0xFFFFu, hi = x >> 16;
        if ((lo == 0u || lo == 0x3F80u) && (hi == 0u || hi == 0x3F80u)) f |= 4u; // bf16
        else f |= 8u;
    }
    if (f) atomicOr(&g_flags, f);
}

__global__ void k_finalize_mask() {
    unsigned fl = g_flags;
    int m;
    if      (fl & 4u) m = 3;   // bf16
    else if (fl & 1u) m = 0;   // float32
    else if (fl & 2u) m = 1;   // uint8/bool
    else              m = 2;   // int32 (words only 0/1) or degenerate
    g_mask_mode = m;
}

__device__ __forceinline__ bool mask_at(const void* m, int mode, size_t idx) {
    if (mode == 0) return ((const float*)m)[idx] != 0.0f;
    if (mode == 1) return ((const unsigned char*)m)[idx] != 0;
    if (mode == 3) return ((const unsigned short*)m)[idx] != 0;
    return ((const int*)m)[idx] != 0;
}

// ---------------------------------------------------------------------------
// Register-tiled SGEMM: C[M,N] = A[M,K] @ W[K,N] (+bias, layout epilogue)
// MODE 0: write to [b,h,s,64] head layout with scale applied to (acc+bias)
// MODE 1: plain row-major [M,N] + bias
// ---------------------------------------------------------------------------
template <int MODE>
__global__ __launch_bounds__(256, 2) void k_sgemm128(
    const float* __restrict__ A, const float* __restrict__ W,
    const float* __restrict__ bias, float scale,
    float* __restrict__ out, int M, int N, int K)
{
    __shared__ float As[8][128];   // transposed A tile
    __shared__ float Bs[8][128];
    const int tid = threadIdx.x;
    const int m0 = blockIdx.y * 128, n0 = blockIdx.x * 128;
    const int arow = tid >> 1, acol = (tid & 1) * 4;
    const int brow = tid >> 5, bcol = (tid & 31) * 4;
    const float* Ap = A + (size_t)(m0 + arow) * K + acol;
    const float* Wp = W + (size_t)brow * N + n0 + bcol;
    const int tr = (tid >> 4) * 8, tc = (tid & 15) * 8;

    float acc[8][8];
#pragma unroll
    for (int i = 0; i < 8; i++)
#pragma unroll
        for (int j = 0; j < 8; j++) acc[i][j] = 0.f;

    for (int k0 = 0; k0 < K; k0 += 8) {
        float4 a = *(const float4*)Ap; Ap += 8;
        As[acol + 0][arow] = a.x; As[acol + 1][arow] = a.y;
        As[acol + 2][arow] = a.z; As[acol + 3][arow] = a.w;
        *(float4*)&Bs[brow][bcol] = *(const float4*)Wp; Wp += (size_t)8 * N;
        __syncthreads();
#pragma unroll
        for (int d = 0; d < 8; d++) {
            float ra[8], rb[8];
            *(float4*)&ra[0] = *(float4*)&As[d][tr];
            *(float4*)&ra[4] = *(float4*)&As[d][tr + 4];
            *(float4*)&rb[0] = *(float4*)&Bs[d][tc];
            *(float4*)&rb[4] = *(float4*)&Bs[d][tc + 4];
#pragma unroll
            for (int i = 0; i < 8; i++)
#pragma unroll
                for (int j = 0; j < 8; j++) acc[i][j] += ra[i] * rb[j];
        }
        __syncthreads();
    }

    if (MODE == 0) {
#pragma unroll
        for (int i = 0; i < 8; i++) {
            int row = m0 + tr + i;
            int bb = row >> 10, ss = row & 1023;
#pragma unroll
            for (int j = 0; j < 8; j++) {
                int col = n0 + tc + j;
                float v = (acc[i][j] + bias[col]) * scale;
                int hh = col >> 6, dk = col & 63;
                out[(((size_t)(bb * H_ + hh) << 10) + ss) * 64 + dk] = v;
            }
        }
    } else {
#pragma unroll
        for (int i = 0; i < 8; i++) {
            int row = m0 + tr + i;
#pragma unroll
            for (int j = 0; j < 8; j++) {
                int col = n0 + tc + j;
                out[(size_t)row * N + col] = acc[i][j] + bias[col];
            }
        }
    }
}

// ---------------------------------------------------------------------------
// qrel[bhs][t] = sum_d qp[bhs][d] * rel_k[t][d]   (q already scaled)
// ---------------------------------------------------------------------------
__global__ __launch_bounds__(256) void k_qrel(const float* __restrict__ qp,
                                              const float* __restrict__ rel_k,
                                              float* __restrict__ qrel)
{
    __shared__ float rk[V_ * 65];   // padded stride 65 -> conflict-free
    __shared__ float qs[8 * DK_];
    const int tid = threadIdx.x;
    const long long r0 = (long long)blockIdx.x * 8;
    for (int i = tid; i < V_ * DK_; i += 256) {
        int t = i / DK_, d = i % DK_;
        rk[t * 65 + d] = rel_k[i];
    }
    for (int i = tid; i < 8 * DK_; i += 256) qs[i] = qp[r0 * DK_ + i];
    __syncthreads();
    const int wr = tid >> 5, lane = tid & 31;
    for (int t = lane; t < V_; t += 32) {
        float s = 0.f;
#pragma unroll
        for (int d = 0; d < DK_; d++) s += qs[wr * DK_ + d] * rk[t * 65 + d];
        qrel[(r0 + wr) * V_ + t] = s;
    }
}

// ---------------------------------------------------------------------------
// QK: scores[bh][q][k] = q.k + qrel[t(k-q)], masked & adj-log folded
// grid (S/128 ktiles, S/128 qtiles, BH), 64KB dyn smem
// ---------------------------------------------------------------------------
__global__ __launch_bounds__(256, 2) void k_qk(
    const float* __restrict__ qp, const float* __restrict__ kp,
    const float* __restrict__ qrel, const void* __restrict__ mask,
    const float* __restrict__ adj, float* __restrict__ scores)
{
    extern __shared__ float sh[];
    float* Qs = sh;              // [64][128] transposed
    float* Ks = sh + 64 * 128;
    const int tid = threadIdx.x;
    const int bh = blockIdx.z;
    const int q0 = blockIdx.y * 128, k0 = blockIdx.x * 128;
    const size_t qbase = ((size_t)bh * S_ + q0) * DK_;
    const size_t kbase = ((size_t)bh * S_ + k0) * DK_;
    const int lr = tid >> 4;
    const int lc = (tid & 15) * 4;
#pragma unroll
    for (int it = 0; it < 8; it++) {
        int row = it * 16 + lr;
        float4 a = *(const float4*)(qp + qbase + (size_t)row * DK_ + lc);
        Qs[(lc + 0) * 128 + row] = a.x; Qs[(lc + 1) * 128 + row] = a.y;
        Qs[(lc + 2) * 128 + row] = a.z; Qs[(lc + 3) * 128 + row] = a.w;
        float4 b = *(const float4*)(kp + kbase + (size_t)row * DK_ + lc);
        Ks[(lc + 0) * 128 + row] = b.x; Ks[(lc + 1) * 128 + row] = b.y;
        Ks[(lc + 2) * 128 + row] = b.z; Ks[(lc + 3) * 128 + row] = b.w;
    }
    __syncthreads();

    const int tr = (tid >> 4) * 8, tc = (tid & 15) * 8;
    float acc[8][8];
#pragma unroll
    for (int i = 0; i < 8; i++)
#pragma unroll
        for (int j = 0; j < 8; j++) acc[i][j] = 0.f;

#pragma unroll 16
    for (int d = 0; d < 64; d++) {
        float ra[8], rb[8];
        *(float4*)&ra[0] = *(float4*)&Qs[d * 128 + tr];
        *(float4*)&ra[4] = *(float4*)&Qs[d * 128 + tr + 4];
        *(float4*)&rb[0] = *(float4*)&Ks[d * 128 + tc];
        *(float4*)&rb[4] = *(float4*)&Ks[d * 128 + tc + 4];
#pragma unroll
        for (int i = 0; i < 8; i++)
#pragma unroll
            for (int j = 0; j < 8; j++) acc[i][j] += ra[i] * rb[j];
    }

    const int mode = g_mask_mode;
    const int bb = bh >> 4;
#pragma unroll
    for (int i = 0; i < 8; i++) {
        int q = q0 + tr + i;
        const float* qr = qrel + ((size_t)bh * S_ + q) * V_;
        size_t mrow = ((size_t)bb * S_ + q) * S_;
        size_t arow = ((size_t)bh * S_ + q) * S_;
#pragma unroll
        for (int j = 0; j < 8; j++) {
            int k = k0 + tc + j;
            int dist = k - q;
            dist = dist < -32 ? -32 : (dist > 32 ? 32 : dist);
            float s = acc[i][j] + qr[dist + 32];
            float av = adj[arow + k];
            bool mm = mask_at(mask, mode, mrow + k);
            if (mm || av == 0.0f) s = -1e30f;
            else if (av != 1.0f)  s -= __logf(av);   // fold 1/adj into softmax
            scores[arow + k] = s;
        }
    }
}

// ---------------------------------------------------------------------------
// Softmax (warp per row) + rel-value buckets; attn written in-place + to d_out
// ---------------------------------------------------------------------------
__global__ __launch_bounds__(256) void k_softmax(float* __restrict__ scores,
                                                 float* __restrict__ wbuf,
                                                 float* __restrict__ attn_out)
{
    const int lane = threadIdx.x & 31;
    const long long row = (long long)blockIdx.x * 8 + (threadIdx.x >> 5);
    float* srow = scores + (size_t)row * S_;
    float4 v[8];
#pragma unroll
    for (int i = 0; i < 8; i++) v[i] = *(const float4*)(srow + i * 128 + lane * 4);

    float mx = -3.4e38f;
#pragma unroll
    for (int i = 0; i < 8; i++) {
        mx = fmaxf(mx, fmaxf(fmaxf(v[i].x, v[i].y), fmaxf(v[i].z, v[i].w)));
    }
#pragma unroll
    for (int o = 16; o; o >>= 1) mx = fmaxf(mx, __shfl_xor_sync(0xffffffffu, mx, o));

    float sum = 0.f;
#pragma unroll
    for (int i = 0; i < 8; i++) {
        v[i].x = __expf(v[i].x - mx); v[i].y = __expf(v[i].y - mx);
        v[i].z = __expf(v[i].z - mx); v[i].w = __expf(v[i].w - mx);
        sum += v[i].x + v[i].y + v[i].z + v[i].w;
    }
#pragma unroll
    for (int o = 16; o; o >>= 1) sum += __shfl_xor_sync(0xffffffffu, sum, o);
    float inv = sum > 0.f ? 1.f / sum : 0.f;

    const int q = (int)(row & 1023);
    float* wrow = wbuf + (size_t)row * V_;
    for (int t = lane; t < V_; t += 32) wrow[t] = 0.f;
    __syncwarp();

    float* arow = attn_out ? attn_out + (size_t)row * S_ : nullptr;
    float pre = 0.f, suf = 0.f;
#pragma unroll
    for (int i = 0; i < 8; i++) {
        int kb = i * 128 + lane * 4;
        v[i].x *= inv; v[i].y *= inv; v[i].z *= inv; v[i].w *= inv;
        float vals[4] = {v[i].x, v[i].y, v[i].z, v[i].w};
#pragma unroll
        for (int j = 0; j < 4; j++) {
            int k = kb + j;
            if (k <= q - 32)      pre += vals[j];
            else if (k >= q + 32) suf += vals[j];
            else                  wrow[k - q + 32] = vals[j];  // single-elem bucket
        }
        *(float4*)(srow + kb) = v[i];
        if (arow) *(float4*)(arow + kb) = v[i];
    }
#pragma unroll
    for (int o = 16; o; o >>= 1) {
        pre += __shfl_xor_sync(0xffffffffu, pre, o);
        suf += __shfl_xor_sync(0xffffffffu, suf, o);
    }
    if (lane == 0) { wrow[0] = pre; wrow[64] = suf; }
}

// ---------------------------------------------------------------------------
// AV: ctx[bh][q][d] = sum_k attn[q][k] * vp[k][d]  -> stored [b][s][h*64+d]
// ---------------------------------------------------------------------------
__global__ __launch_bounds__(256) void k_av(const float* __restrict__ attn,
                                            const float* __restrict__ vp,
                                            float* __restrict__ ctx)
{
    __shared__ float As[128 * 32];
    __shared__ float Vs[32 * 64];
    const int tid = threadIdx.x;
    const int bh = blockIdx.y;
    const int q0 = blockIdx.x * 128;
    const int tr8 = (tid >> 4) * 8;
    const int tc4 = (tid & 15) * 4;
    float acc[8][4];
#pragma unroll
    for (int i = 0; i < 8; i++)
#pragma unroll
        for (int j = 0; j < 4; j++) acc[i][j] = 0.f;

    const size_t abase = ((size_t)bh * S_ + q0) * S_;
    const size_t vbase = (size_t)bh * S_ * DK_;
    for (int kt = 0; kt < S_; kt += 32) {
#pragma unroll
        for (int p = 0; p < 4; p++) {
            int row = p * 32 + (tid >> 3);
            int c4 = (tid & 7) * 4;
            *(float4*)&As[row * 32 + c4] =
                *(const float4*)(attn + abase + (size_t)row * S_ + kt + c4);
        }
#pragma unroll
        for (int p = 0; p < 2; p++) {
            int row = p * 16 + (tid >> 4);
            int c4 = (tid & 15) * 4;
            *(float4*)&Vs[row * 64 + c4] =
                *(const float4*)(vp + vbase + (size_t)(kt + row) * DK_ + c4);
        }
        __syncthreads();
#pragma unroll 8
        for (int kk = 0; kk < 32; kk++) {
            float4 bv = *(float4*)&Vs[kk * 64 + tc4];
#pragma unroll
            for (int i = 0; i < 8; i++) {
                float a = As[(tr8 + i) * 32 + kk];
                acc[i][0] += a * bv.x; acc[i][1] += a * bv.y;
                acc[i][2] += a * bv.z; acc[i][3] += a * bv.w;
            }
        }
        __syncthreads();
    }
    const int bb = bh >> 4, hh = bh & 15;
#pragma unroll
    for (int i = 0; i < 8; i++) {
        int q = q0 + tr8 + i;
        float4 o = make_float4(acc[i][0], acc[i][1], acc[i][2], acc[i][3]);
        *(float4*)(ctx + ((size_t)(bb * S_ + q)) * D_ + hh * 64 + tc4) = o;
    }
}

// ---------------------------------------------------------------------------
// ctx += w @ rel_v   (65x64 per row)
// ---------------------------------------------------------------------------
__global__ __launch_bounds__(256) void k_relctx(const float* __restrict__ wbuf,
                                                const float* __restrict__ rel_v,
                                                float* __restrict__ ctx)
{
    __shared__ float rv[V_ * 64];
    __shared__ float ws[4][V_];
    const int tid = threadIdx.x;
    const long long r0 = (long long)blockIdx.x * 4;
    for (int i = tid; i < V_ * 64; i += 256) rv[i] = rel_v[i];
    for (int i = tid; i < 4 * V_; i += 256)
        ws[i / V_][i % V_] = wbuf[(r0 + i / V_) * V_ + i % V_];
    __syncthreads();
    const int rr = tid >> 6;
    const int d = tid & 63;
    float acc = 0.f;
#pragma unroll
    for (int t = 0; t < V_; t++) acc += ws[rr][t] * rv[t * 64 + d];
    long long r = r0 + rr;
    int bh = (int)(r >> 10), s = (int)(r & 1023);
    int bb = bh >> 4, hh = bh & 15;
    ctx[((size_t)(bb * S_ + s)) * D_ + hh * 64 + d] += acc;
}

// ---------------------------------------------------------------------------
// Launch
// ---------------------------------------------------------------------------
extern "C" void kernel_launch(void* const* d_in, const int* in_sizes, int n_in,
                              void* d_out, int out_size)
{
    const float* key   = (const float*)d_in[0];
    const float* value = (const float*)d_in[1];
    const float* query = (const float*)d_in[2];
    const void*  mask  = d_in[3];
    const float* adj   = (const float*)d_in[4];
    const float* Wq = (const float*)d_in[5];
    const float* bq = (const float*)d_in[6];
    const float* Wk = (const float*)d_in[7];
    const float* bk = (const float*)d_in[8];
    const float* Wv = (const float*)d_in[9];
    const float* bv = (const float*)d_in[10];
    const float* Wo = (const float*)d_in[11];
    const float* bo = (const float*)d_in[12];
    const float* rel_k = (const float*)d_in[13];
    const float* rel_v = (const float*)d_in[14];
    float* outF = (float*)d_out;

    float *qp, *kp, *vp, *qrel, *wb, *sc, *ctx;
    cudaGetSymbolAddress((void**)&qp,   g_qp);
    cudaGetSymbolAddress((void**)&kp,   g_kp);
    cudaGetSymbolAddress((void**)&vp,   g_vp);
    cudaGetSymbolAddress((void**)&qrel, g_qrel);
    cudaGetSymbolAddress((void**)&wb,   g_w);
    cudaGetSymbolAddress((void**)&sc,   g_scores);
    cudaGetSymbolAddress((void**)&ctx,  g_ctx);

    cudaFuncSetAttribute(k_qk, cudaFuncAttributeMaxDynamicSharedMemorySize, 64 * 1024);

    // mask dtype detection (first 8MB is safe under every dtype hypothesis)
    k_reset_flags<<<1, 1>>>();
    k_detect_mask<<<256, 256>>>((const unsigned*)mask, in_sizes[3] / 4);
    k_finalize_mask<<<1, 1>>>();

    // projections (q pre-scaled by 1/sqrt(DK) incl. bias, matching reference)
    dim3 pg(D_ / 128, MROWS / 128);
    k_sgemm128<0><<<pg, 256>>>(query, Wq, bq, 0.125f, qp, MROWS, D_, D_);
    k_sgemm128<0><<<pg, 256>>>(key,   Wk, bk, 1.0f,   kp, MROWS, D_, D_);
    k_sgemm128<0><<<pg, 256>>>(value, Wv, bv, 1.0f,   vp, MROWS, D_, D_);

    // relative-key projection (rank-65 trick)
    k_qrel<<<NROW / 8, 256>>>(qp, rel_k, qrel);

    // scores + mask + adj fold
    dim3 qkg(S_ / 128, S_ / 128, BH_);
    k_qk<<<qkg, 256, 64 * 1024>>>(qp, kp, qrel, mask, adj, sc);

    // softmax + buckets (+ attn output if the harness expects it)
    bool hasAttn = out_size >= (int)(FINAL_ELEMS + SCORES_ELEMS);
    float* attnOut = hasAttn ? outF + FINAL_ELEMS : nullptr;
    k_softmax<<<NROW / 8, 256>>>(sc, wb, attnOut);

    // context
    dim3 avg(S_ / 128, BH_);
    k_av<<<avg, 256>>>(sc, vp, ctx);
    k_relctx<<<NROW / 4, 256>>>(wb, rel_v, ctx);

    // output projection
    k_sgemm128<1><<<pg, 256>>>(ctx, Wo, bo, 1.0f, outF, MROWS, D_, D_);
}

// round 7
// speedup vs baseline: 1.5101x; 1.5101x over previous
#include <cuda_runtime.h>
#include <cuda_bf16.h>
#include <cstdint>

// ---------------------------------------------------------------------------
// Problem constants
// ---------------------------------------------------------------------------
static constexpr int B_  = 8;
static constexpr int S_  = 1024;
static constexpr int D_  = 1024;
static constexpr int H_  = 16;
static constexpr int DK_ = 64;
static constexpr int V_  = 65;            // 2*MAXREL+1
static constexpr int BH_ = B_ * H_;       // 128
static constexpr int MROWS = B_ * S_;     // 8192
static constexpr int NROW  = BH_ * S_;    // 131072 (b,h,s) rows
static constexpr size_t SCORES_ELEMS = (size_t)BH_ * S_ * S_;  // 134217728
static constexpr int FINAL_ELEMS = MROWS * D_;                 // 8388608

// ---------------------------------------------------------------------------
// Device scratch (static — no allocation allowed)
// ---------------------------------------------------------------------------
__device__ float g_qp[BH_ * S_ * DK_];     // Q projection, [bh][s][d], pre-scaled 1/8
__device__ float g_kp[BH_ * S_ * DK_];
__device__ float g_vp[BH_ * S_ * DK_];
__device__ float g_qrel[NROW * V_];        // q . rel_k[t]
__device__ float g_w[NROW * V_];           // relative-value buckets
__device__ float g_scores[SCORES_ELEMS];   // scores, then attn in-place
__device__ float g_ctx[MROWS * D_];        // [b][s][h*64+d]
__device__ unsigned g_flags;
__device__ int g_mask_mode;

// bf16 split-precision fragment images (mma.sync m16n8k16 register order)
// A image words: 8192*1024/2 = 4.19M u32 ; W image: 1024*1024/2 = 524288 u32
__device__ uint32_t g_Ahi[MROWS * D_ / 2];   // 16MB
__device__ uint32_t g_Alo[MROWS * D_ / 2];   // 16MB
__device__ uint32_t g_Whi[D_ * D_ / 2];      // 2MB
__device__ uint32_t g_Wlo[D_ * D_ / 2];      // 2MB

// ---------------------------------------------------------------------------
// bf16 split helpers
// ---------------------------------------------------------------------------
__device__ __forceinline__ void split_pair(float x0, float x1,
                                           uint32_t& h, uint32_t& l) {
    __nv_bfloat16 h0 = __float2bfloat16(x0);
    __nv_bfloat16 h1 = __float2bfloat16(x1);
    __nv_bfloat16 l0 = __float2bfloat16(x0 - __bfloat162float(h0));
    __nv_bfloat16 l1 = __float2bfloat16(x1 - __bfloat162float(h1));
    h = (uint32_t)__bfloat16_as_ushort(h0) | ((uint32_t)__bfloat16_as_ushort(h1) << 16);
    l = (uint32_t)__bfloat16_as_ushort(l0) | ((uint32_t)__bfloat16_as_ushort(l1) << 16);
}

// mma.sync m16n8k16 bf16: C += A*B (A row-major 16x16, B col-major 16x8)
__device__ __forceinline__ void mma_bf16(float* c,
                                         uint32_t a0, uint32_t a1, uint32_t a2, uint32_t a3,
                                         uint32_t b0, uint32_t b1) {
    asm volatile(
        "mma.sync.aligned.m16n8k16.row.col.f32.bf16.bf16.f32 "
        "{%0,%1,%2,%3}, {%4,%5,%6,%7}, {%8,%9}, {%0,%1,%2,%3};"
        : "+f"(c[0]), "+f"(c[1]), "+f"(c[2]), "+f"(c[3])
        : "r"(a0), "r"(a1), "r"(a2), "r"(a3), "r"(b0), "r"(b1));
}

// ---------------------------------------------------------------------------
// Mask dtype detection (bool serialization is ambiguous: f32/u8/i32/bf16)
// ---------------------------------------------------------------------------
__global__ void k_reset_flags() { g_flags = 0u; }

__global__ void k_detect_mask(const unsigned* __restrict__ w, int n) {
    unsigned f = 0;
    for (int i = blockIdx.x * blockDim.x + threadIdx.x; i < n;
         i += gridDim.x * blockDim.x) {
        unsigned x = w[i];
        if (x == 0u) continue;
        if (x == 0x3F800000u) { f |= 1u; continue; }
        if ((x & ~0x01010101u) == 0u) { f |= (x == 1u) ? 16u : 2u; continue; }
        unsigned lo = x & 0xFFFFu, hi = x >> 16;
        if ((lo == 0u || lo == 0x3F80u) && (hi == 0u || hi == 0x3F80u)) f |= 4u;
        else f |= 8u;
    }
    if (f) atomicOr(&g_flags, f);
}

__global__ void k_finalize_mask() {
    unsigned fl = g_flags;
    int m;
    if      (fl & 4u) m = 3;
    else if (fl & 1u) m = 0;
    else if (fl & 2u) m = 1;
    else              m = 2;
    g_mask_mode = m;
}

__device__ __forceinline__ bool mask_at(const void* m, int mode, size_t idx) {
    if (mode == 0) return ((const float*)m)[idx] != 0.0f;
    if (mode == 1) return ((const unsigned char*)m)[idx] != 0;
    if (mode == 3) return ((const unsigned short*)m)[idx] != 0;
    return ((const int*)m)[idx] != 0;
}

// ---------------------------------------------------------------------------
// Pack A[8192,1024] fp32 -> hi/lo fragment images.
// Word idx = ((mblk*64 + ks)*32 + lane)*4 + r,
//   r: 0 -> (row+0, col+0), 1 -> (row+8, col+0), 2 -> (row+0, col+8), 3 -> (row+8, col+8)
//   row = mblk*16 + lane/4 (+8 per r&1), col = ks*16 + (lane%4)*2 (+8 per r>>1)
// ---------------------------------------------------------------------------
__global__ __launch_bounds__(256) void k_pack_a(
    const float* __restrict__ src,
    uint32_t* __restrict__ hi, uint32_t* __restrict__ lo)
{
    int idx = blockIdx.x * 256 + threadIdx.x;       // 4.19M words
    int r    = idx & 3;
    int lane = (idx >> 2) & 31;
    int ks   = (idx >> 7) & 63;
    int mblk = idx >> 13;
    int row = mblk * 16 + (lane >> 2) + (r & 1) * 8;
    int col = ks * 16 + (lane & 3) * 2 + (r >> 1) * 8;
    float2 x = *(const float2*)(src + (size_t)row * 1024 + col);
    uint32_t h, l;
    split_pair(x.x, x.y, h, l);
    hi[idx] = h; lo[idx] = l;
}

// ---------------------------------------------------------------------------
// Pack W[1024k,1024n] fp32 -> hi/lo B fragment images (col-major operand).
// Word idx = ((n16*64 + ks)*32 + lane)*4 + r,
//   n = n16*16 + (r>>1)*8 + lane/4, k = ks*16 + (lane%4)*2 + (r&1)*8
//   pair packs (W[k][n], W[k+1][n]) — consecutive k in one b32.
// ---------------------------------------------------------------------------
__global__ __launch_bounds__(256) void k_pack_w(
    const float* __restrict__ W,
    uint32_t* __restrict__ hi, uint32_t* __restrict__ lo)
{
    int idx = blockIdx.x * 256 + threadIdx.x;       // 524288 words
    int r    = idx & 3;
    int lane = (idx >> 2) & 31;
    int ks   = (idx >> 7) & 63;
    int n16  = idx >> 13;
    int n = n16 * 16 + (r >> 1) * 8 + (lane >> 2);
    int k = ks * 16 + (lane & 3) * 2 + (r & 1) * 8;
    float x0 = W[(size_t)k * 1024 + n];
    float x1 = W[(size_t)(k + 1) * 1024 + n];
    uint32_t h, l;
    split_pair(x0, x1, h, l);
    hi[idx] = h; lo[idx] = l;
}

// ---------------------------------------------------------------------------
// Tensor-core split-bf16 GEMM: C[8192,1024] = A @ W (+bias, epilogue layout)
// CTA: 128x128 tile, 8 warps (2m x 4n), warp tile 64x32.
// Per kstep: 12 ldg.128 (fragment images), 48 mma (hi*hi + lo*hi + hi*lo).
// MODE 0: write to [b,h,s,64] head layout with (acc+bias)*scale
// MODE 1: row-major [M,N] + bias
// ---------------------------------------------------------------------------
template <int MODE>
__global__ __launch_bounds__(256) void k_mma_gemm(
    const uint4* __restrict__ Ahi, const uint4* __restrict__ Alo,
    const uint4* __restrict__ Bhi, const uint4* __restrict__ Blo,
    const float* __restrict__ bias, float scale, float* __restrict__ out)
{
    const int tid = threadIdx.x, lane = tid & 31, wid = tid >> 5;
    const int warp_m = wid & 1, warp_n = wid >> 1;
    const int ntile = blockIdx.x, mtile = blockIdx.y;
    const int mb0 = mtile * 8 + warp_m * 4;   // 16-row units
    const int nb0 = ntile * 8 + warp_n * 2;   // 16-col units

    float acc[4][4][4];
#pragma unroll
    for (int i = 0; i < 4; i++)
#pragma unroll
        for (int j = 0; j < 4; j++)
#pragma unroll
            for (int c = 0; c < 4; c++) acc[i][j][c] = 0.f;

    uint4 ah[2][4], al[2][4], bh[2][2], bl[2][2];

    // prime kstep 0
#pragma unroll
    for (int i = 0; i < 4; i++) {
        ah[0][i] = Ahi[((size_t)(mb0 + i) * 64 + 0) * 32 + lane];
        al[0][i] = Alo[((size_t)(mb0 + i) * 64 + 0) * 32 + lane];
    }
#pragma unroll
    for (int j = 0; j < 2; j++) {
        bh[0][j] = Bhi[((size_t)(nb0 + j) * 64 + 0) * 32 + lane];
        bl[0][j] = Blo[((size_t)(nb0 + j) * 64 + 0) * 32 + lane];
    }

#pragma unroll 2
    for (int ks = 0; ks < 64; ks++) {
        const int cb = ks & 1, nb = cb ^ 1;
        if (ks + 1 < 64) {
#pragma unroll
            for (int i = 0; i < 4; i++) {
                ah[nb][i] = Ahi[((size_t)(mb0 + i) * 64 + ks + 1) * 32 + lane];
                al[nb][i] = Alo[((size_t)(mb0 + i) * 64 + ks + 1) * 32 + lane];
            }
#pragma unroll
            for (int j = 0; j < 2; j++) {
                bh[nb][j] = Bhi[((size_t)(nb0 + j) * 64 + ks + 1) * 32 + lane];
                bl[nb][j] = Blo[((size_t)(nb0 + j) * 64 + ks + 1) * 32 + lane];
            }
        }
#pragma unroll
        for (int i = 0; i < 4; i++) {
            const uint4 A = ah[cb][i], L = al[cb][i];
#pragma unroll
            for (int j = 0; j < 2; j++) {
                const uint4 Bh = bh[cb][j], Bl = bl[cb][j];
                // n8 even (regs .x,.y)
                mma_bf16(acc[i][j * 2], A.x, A.y, A.z, A.w, Bh.x, Bh.y);
                mma_bf16(acc[i][j * 2], L.x, L.y, L.z, L.w, Bh.x, Bh.y);
                mma_bf16(acc[i][j * 2], A.x, A.y, A.z, A.w, Bl.x, Bl.y);
                // n8 odd (regs .z,.w)
                mma_bf16(acc[i][j * 2 + 1], A.x, A.y, A.z, A.w, Bh.z, Bh.w);
                mma_bf16(acc[i][j * 2 + 1], L.x, L.y, L.z, L.w, Bh.z, Bh.w);
                mma_bf16(acc[i][j * 2 + 1], A.x, A.y, A.z, A.w, Bl.z, Bl.w);
            }
        }
    }

    // epilogue: c0/c1 -> (row, col..col+1), c2/c3 -> (row+8, col..col+1)
#pragma unroll
    for (int i = 0; i < 4; i++) {
        const int row0 = mtile * 128 + warp_m * 64 + i * 16 + (lane >> 2);
#pragma unroll
        for (int j = 0; j < 4; j++) {
            const int col0 = ntile * 128 + warp_n * 32 + j * 8 + (lane & 3) * 2;
            const float b0 = bias[col0], b1 = bias[col0 + 1];
#pragma unroll
            for (int half = 0; half < 2; half++) {
                const int row = row0 + half * 8;
                float v0 = acc[i][j][half * 2 + 0] + b0;
                float v1 = acc[i][j][half * 2 + 1] + b1;
                if (MODE == 0) {
                    v0 *= scale; v1 *= scale;
                    const int bb = row >> 10, ss = row & 1023;
                    const int hh = col0 >> 6, dk = col0 & 63;
                    float* dst = out + ((((size_t)(bb * 16 + hh)) << 10) + ss) * 64 + dk;
                    *(float2*)dst = make_float2(v0, v1);
                } else {
                    *(float2*)(out + (size_t)row * 1024 + col0) = make_float2(v0, v1);
                }
            }
        }
    }
}

// ---------------------------------------------------------------------------
// qrel[bhs][t] = sum_d qp[bhs][d] * rel_k[t][d]   (q already scaled)
// ---------------------------------------------------------------------------
__global__ __launch_bounds__(256) void k_qrel(const float* __restrict__ qp,
                                              const float* __restrict__ rel_k,
                                              float* __restrict__ qrel)
{
    __shared__ float rk[V_ * 65];
    __shared__ float qs[8 * DK_];
    const int tid = threadIdx.x;
    const long long r0 = (long long)blockIdx.x * 8;
    for (int i = tid; i < V_ * DK_; i += 256) {
        int t = i / DK_, d = i % DK_;
        rk[t * 65 + d] = rel_k[i];
    }
    for (int i = tid; i < 8 * DK_; i += 256) qs[i] = qp[r0 * DK_ + i];
    __syncthreads();
    const int wr = tid >> 5, lane = tid & 31;
    for (int t = lane; t < V_; t += 32) {
        float s = 0.f;
#pragma unroll
        for (int d = 0; d < DK_; d++) s += qs[wr * DK_ + d] * rk[t * 65 + d];
        qrel[(r0 + wr) * V_ + t] = s;
    }
}

// ---------------------------------------------------------------------------
// QK: scores[bh][q][k] = q.k + qrel[t(k-q)], masked & adj-log folded
// ---------------------------------------------------------------------------
__global__ __launch_bounds__(256, 2) void k_qk(
    const float* __restrict__ qp, const float* __restrict__ kp,
    const float* __restrict__ qrel, const void* __restrict__ mask,
    const float* __restrict__ adj, float* __restrict__ scores)
{
    extern __shared__ float sh[];
    float* Qs = sh;
    float* Ks = sh + 64 * 128;
    const int tid = threadIdx.x;
    const int bh = blockIdx.z;
    const int q0 = blockIdx.y * 128, k0 = blockIdx.x * 128;
    const size_t qbase = ((size_t)bh * S_ + q0) * DK_;
    const size_t kbase = ((size_t)bh * S_ + k0) * DK_;
    const int lr = tid >> 4;
    const int lc = (tid & 15) * 4;
#pragma unroll
    for (int it = 0; it < 8; it++) {
        int row = it * 16 + lr;
        float4 a = *(const float4*)(qp + qbase + (size_t)row * DK_ + lc);
        Qs[(lc + 0) * 128 + row] = a.x; Qs[(lc + 1) * 128 + row] = a.y;
        Qs[(lc + 2) * 128 + row] = a.z; Qs[(lc + 3) * 128 + row] = a.w;
        float4 b = *(const float4*)(kp + kbase + (size_t)row * DK_ + lc);
        Ks[(lc + 0) * 128 + row] = b.x; Ks[(lc + 1) * 128 + row] = b.y;
        Ks[(lc + 2) * 128 + row] = b.z; Ks[(lc + 3) * 128 + row] = b.w;
    }
    __syncthreads();

    const int tr = (tid >> 4) * 8, tc = (tid & 15) * 8;
    float acc[8][8];
#pragma unroll
    for (int i = 0; i < 8; i++)
#pragma unroll
        for (int j = 0; j < 8; j++) acc[i][j] = 0.f;

#pragma unroll 16
    for (int d = 0; d < 64; d++) {
        float ra[8], rb[8];
        *(float4*)&ra[0] = *(float4*)&Qs[d * 128 + tr];
        *(float4*)&ra[4] = *(float4*)&Qs[d * 128 + tr + 4];
        *(float4*)&rb[0] = *(float4*)&Ks[d * 128 + tc];
        *(float4*)&rb[4] = *(float4*)&Ks[d * 128 + tc + 4];
#pragma unroll
        for (int i = 0; i < 8; i++)
#pragma unroll
            for (int j = 0; j < 8; j++) acc[i][j] += ra[i] * rb[j];
    }

    const int mode = g_mask_mode;
    const int bb = bh >> 4;
#pragma unroll
    for (int i = 0; i < 8; i++) {
        int q = q0 + tr + i;
        const float* qr = qrel + ((size_t)bh * S_ + q) * V_;
        size_t mrow = ((size_t)bb * S_ + q) * S_;
        size_t arow = ((size_t)bh * S_ + q) * S_;
#pragma unroll
        for (int j = 0; j < 8; j++) {
            int k = k0 + tc + j;
            int dist = k - q;
            dist = dist < -32 ? -32 : (dist > 32 ? 32 : dist);
            float s = acc[i][j] + qr[dist + 32];
            float av = adj[arow + k];
            bool mm = mask_at(mask, mode, mrow + k);
            if (mm || av == 0.0f) s = -1e30f;
            else if (av != 1.0f)  s -= __logf(av);
            scores[arow + k] = s;
        }
    }
}

// ---------------------------------------------------------------------------
// Softmax (warp per row) + rel-value buckets; attn written in-place + to d_out
// ---------------------------------------------------------------------------
__global__ __launch_bounds__(256) void k_softmax(float* __restrict__ scores,
                                                 float* __restrict__ wbuf,
                                                 float* __restrict__ attn_out)
{
    const int lane = threadIdx.x & 31;
    const long long row = (long long)blockIdx.x * 8 + (threadIdx.x >> 5);
    float* srow = scores + (size_t)row * S_;
    float4 v[8];
#pragma unroll
    for (int i = 0; i < 8; i++) v[i] = *(const float4*)(srow + i * 128 + lane * 4);

    float mx = -3.4e38f;
#pragma unroll
    for (int i = 0; i < 8; i++) {
        mx = fmaxf(mx, fmaxf(fmaxf(v[i].x, v[i].y), fmaxf(v[i].z, v[i].w)));
    }
#pragma unroll
    for (int o = 16; o; o >>= 1) mx = fmaxf(mx, __shfl_xor_sync(0xffffffffu, mx, o));

    float sum = 0.f;
#pragma unroll
    for (int i = 0; i < 8; i++) {
        v[i].x = __expf(v[i].x - mx); v[i].y = __expf(v[i].y - mx);
        v[i].z = __expf(v[i].z - mx); v[i].w = __expf(v[i].w - mx);
        sum += v[i].x + v[i].y + v[i].z + v[i].w;
    }
#pragma unroll
    for (int o = 16; o; o >>= 1) sum += __shfl_xor_sync(0xffffffffu, sum, o);
    float inv = sum > 0.f ? 1.f / sum : 0.f;

    const int q = (int)(row & 1023);
    float* wrow = wbuf + (size_t)row * V_;
    for (int t = lane; t < V_; t += 32) wrow[t] = 0.f;
    __syncwarp();

    float* arow = attn_out ? attn_out + (size_t)row * S_ : nullptr;
    float pre = 0.f, suf = 0.f;
#pragma unroll
    for (int i = 0; i < 8; i++) {
        int kb = i * 128 + lane * 4;
        v[i].x *= inv; v[i].y *= inv; v[i].z *= inv; v[i].w *= inv;
        float vals[4] = {v[i].x, v[i].y, v[i].z, v[i].w};
#pragma unroll
        for (int j = 0; j < 4; j++) {
            int k = kb + j;
            if (k <= q - 32)      pre += vals[j];
            else if (k >= q + 32) suf += vals[j];
            else                  wrow[k - q + 32] = vals[j];
        }
        *(float4*)(srow + kb) = v[i];
        if (arow) *(float4*)(arow + kb) = v[i];
    }
#pragma unroll
    for (int o = 16; o; o >>= 1) {
        pre += __shfl_xor_sync(0xffffffffu, pre, o);
        suf += __shfl_xor_sync(0xffffffffu, suf, o);
    }
    if (lane == 0) { wrow[0] = pre; wrow[64] = suf; }
}

// ---------------------------------------------------------------------------
// AV: ctx[bh][q][d] = sum_k attn[q][k] * vp[k][d]  -> stored [b][s][h*64+d]
// ---------------------------------------------------------------------------
__global__ __launch_bounds__(256) void k_av(const float* __restrict__ attn,
                                            const float* __restrict__ vp,
                                            float* __restrict__ ctx)
{
    __shared__ float As[128 * 32];
    __shared__ float Vs[32 * 64];
    const int tid = threadIdx.x;
    const int bh = blockIdx.y;
    const int q0 = blockIdx.x * 128;
    const int tr8 = (tid >> 4) * 8;
    const int tc4 = (tid & 15) * 4;
    float acc[8][4];
#pragma unroll
    for (int i = 0; i < 8; i++)
#pragma unroll
        for (int j = 0; j < 4; j++) acc[i][j] = 0.f;

    const size_t abase = ((size_t)bh * S_ + q0) * S_;
    const size_t vbase = (size_t)bh * S_ * DK_;
    for (int kt = 0; kt < S_; kt += 32) {
#pragma unroll
        for (int p = 0; p < 4; p++) {
            int row = p * 32 + (tid >> 3);
            int c4 = (tid & 7) * 4;
            *(float4*)&As[row * 32 + c4] =
                *(const float4*)(attn + abase + (size_t)row * S_ + kt + c4);
        }
#pragma unroll
        for (int p = 0; p < 2; p++) {
            int row = p * 16 + (tid >> 4);
            int c4 = (tid & 15) * 4;
            *(float4*)&Vs[row * 64 + c4] =
                *(const float4*)(vp + vbase + (size_t)(kt + row) * DK_ + c4);
        }
        __syncthreads();
#pragma unroll 8
        for (int kk = 0; kk < 32; kk++) {
            float4 bv = *(float4*)&Vs[kk * 64 + tc4];
#pragma unroll
            for (int i = 0; i < 8; i++) {
                float a = As[(tr8 + i) * 32 + kk];
                acc[i][0] += a * bv.x; acc[i][1] += a * bv.y;
                acc[i][2] += a * bv.z; acc[i][3] += a * bv.w;
            }
        }
        __syncthreads();
    }
    const int bb = bh >> 4, hh = bh & 15;
#pragma unroll
    for (int i = 0; i < 8; i++) {
        int q = q0 + tr8 + i;
        float4 o = make_float4(acc[i][0], acc[i][1], acc[i][2], acc[i][3]);
        *(float4*)(ctx + ((size_t)(bb * S_ + q)) * D_ + hh * 64 + tc4) = o;
    }
}

// ---------------------------------------------------------------------------
// ctx += w @ rel_v   (65x64 per row)
// ---------------------------------------------------------------------------
__global__ __launch_bounds__(256) void k_relctx(const float* __restrict__ wbuf,
                                                const float* __restrict__ rel_v,
                                                float* __restrict__ ctx)
{
    __shared__ float rv[V_ * 64];
    __shared__ float ws[4][V_];
    const int tid = threadIdx.x;
    const long long r0 = (long long)blockIdx.x * 4;
    for (int i = tid; i < V_ * 64; i += 256) rv[i] = rel_v[i];
    for (int i = tid; i < 4 * V_; i += 256)
        ws[i / V_][i % V_] = wbuf[(r0 + i / V_) * V_ + i % V_];
    __syncthreads();
    const int rr = tid >> 6;
    const int d = tid & 63;
    float acc = 0.f;
#pragma unroll
    for (int t = 0; t < V_; t++) acc += ws[rr][t] * rv[t * 64 + d];
    long long r = r0 + rr;
    int bh = (int)(r >> 10), s = (int)(r & 1023);
    int bb = bh >> 4, hh = bh & 15;
    ctx[((size_t)(bb * S_ + s)) * D_ + hh * 64 + d] += acc;
}

// ---------------------------------------------------------------------------
// Launch
// ---------------------------------------------------------------------------
extern "C" void kernel_launch(void* const* d_in, const int* in_sizes, int n_in,
                              void* d_out, int out_size)
{
    const float* key   = (const float*)d_in[0];
    const float* value = (const float*)d_in[1];
    const float* query = (const float*)d_in[2];
    const void*  mask  = d_in[3];
    const float* adj   = (const float*)d_in[4];
    const float* Wq = (const float*)d_in[5];
    const float* bq = (const float*)d_in[6];
    const float* Wk = (const float*)d_in[7];
    const float* bk = (const float*)d_in[8];
    const float* Wv = (const float*)d_in[9];
    const float* bv = (const float*)d_in[10];
    const float* Wo = (const float*)d_in[11];
    const float* bo = (const float*)d_in[12];
    const float* rel_k = (const float*)d_in[13];
    const float* rel_v = (const float*)d_in[14];
    float* outF = (float*)d_out;

    float *qp, *kp, *vp, *qrel, *wb, *sc, *ctx;
    uint32_t *ahi, *alo, *whi, *wlo;
    cudaGetSymbolAddress((void**)&qp,   g_qp);
    cudaGetSymbolAddress((void**)&kp,   g_kp);
    cudaGetSymbolAddress((void**)&vp,   g_vp);
    cudaGetSymbolAddress((void**)&qrel, g_qrel);
    cudaGetSymbolAddress((void**)&wb,   g_w);
    cudaGetSymbolAddress((void**)&sc,   g_scores);
    cudaGetSymbolAddress((void**)&ctx,  g_ctx);
    cudaGetSymbolAddress((void**)&ahi,  g_Ahi);
    cudaGetSymbolAddress((void**)&alo,  g_Alo);
    cudaGetSymbolAddress((void**)&whi,  g_Whi);
    cudaGetSymbolAddress((void**)&wlo,  g_Wlo);

    cudaFuncSetAttribute(k_qk, cudaFuncAttributeMaxDynamicSharedMemorySize, 64 * 1024);

    // mask dtype detection
    k_reset_flags<<<1, 1>>>();
    k_detect_mask<<<256, 256>>>((const unsigned*)mask, in_sizes[3] / 4);
    k_finalize_mask<<<1, 1>>>();

    const int APACK_BLOCKS = MROWS * D_ / 2 / 256;   // 16384
    const int WPACK_BLOCKS = D_ * D_ / 2 / 256;      // 2048
    dim3 gg(8, 64);   // (ntiles, mtiles)

    // Q projection (pre-scaled by 1/8 incl. bias)
    k_pack_w<<<WPACK_BLOCKS, 256>>>(Wq, whi, wlo);
    k_pack_a<<<APACK_BLOCKS, 256>>>(query, ahi, alo);
    k_mma_gemm<0><<<gg, 256>>>((const uint4*)ahi, (const uint4*)alo,
                               (const uint4*)whi, (const uint4*)wlo, bq, 0.125f, qp);

    // K projection
    k_pack_w<<<WPACK_BLOCKS, 256>>>(Wk, whi, wlo);
    k_pack_a<<<APACK_BLOCKS, 256>>>(key, ahi, alo);
    k_mma_gemm<0><<<gg, 256>>>((const uint4*)ahi, (const uint4*)alo,
                               (const uint4*)whi, (const uint4*)wlo, bk, 1.0f, kp);

    // V projection
    k_pack_w<<<WPACK_BLOCKS, 256>>>(Wv, whi, wlo);
    k_pack_a<<<APACK_BLOCKS, 256>>>(value, ahi, alo);
    k_mma_gemm<0><<<gg, 256>>>((const uint4*)ahi, (const uint4*)alo,
                               (const uint4*)whi, (const uint4*)wlo, bv, 1.0f, vp);

    // relative-key projection (rank-65 trick)
    k_qrel<<<NROW / 8, 256>>>(qp, rel_k, qrel);

    // scores + mask + adj fold
    dim3 qkg(S_ / 128, S_ / 128, BH_);
    k_qk<<<qkg, 256, 64 * 1024>>>(qp, kp, qrel, mask, adj, sc);

    // softmax + buckets (+ attn output if the harness expects it)
    bool hasAttn = (size_t)out_size >= (size_t)FINAL_ELEMS + SCORES_ELEMS;
    float* attnOut = hasAttn ? outF + FINAL_ELEMS : nullptr;
    k_softmax<<<NROW / 8, 256>>>(sc, wb, attnOut);

    // context
    dim3 avg(S_ / 128, BH_);
    k_av<<<avg, 256>>>(sc, vp, ctx);
    k_relctx<<<NROW / 4, 256>>>(wb, rel_v, ctx);

    // output projection (row-major epilogue)
    k_pack_w<<<WPACK_BLOCKS, 256>>>(Wo, whi, wlo);
    k_pack_a<<<APACK_BLOCKS, 256>>>(ctx, ahi, alo);
    k_mma_gemm<1><<<gg, 256>>>((const uint4*)ahi, (const uint4*)alo,
                               (const uint4*)whi, (const uint4*)wlo, bo, 1.0f, outF);
}

// round 8
// speedup vs baseline: 1.6414x; 1.0870x over previous
#include <cuda_runtime.h>
#include <cuda_bf16.h>
#include <cstdint>

// ---------------------------------------------------------------------------
// Problem constants
// ---------------------------------------------------------------------------
static constexpr int B_  = 8;
static constexpr int S_  = 1024;
static constexpr int D_  = 1024;
static constexpr int H_  = 16;
static constexpr int DK_ = 64;
static constexpr int V_  = 65;            // 2*MAXREL+1
static constexpr int BH_ = B_ * H_;       // 128
static constexpr int MROWS = B_ * S_;     // 8192
static constexpr int NROW  = BH_ * S_;    // 131072 (b,h,s) rows
static constexpr size_t SCORES_ELEMS = (size_t)BH_ * S_ * S_;  // 134217728
static constexpr int FINAL_ELEMS = MROWS * D_;                 // 8388608

// ---------------------------------------------------------------------------
// Device scratch (static — no allocation allowed)
// ---------------------------------------------------------------------------
__device__ float g_qp[BH_ * S_ * DK_];     // Q projection, [bh][s][d], pre-scaled 1/8
__device__ float g_kp[BH_ * S_ * DK_];
__device__ float g_vp[BH_ * S_ * DK_];
__device__ float g_qrel[NROW * V_];        // q . rel_k[t]
__device__ float g_w[NROW * V_];           // relative-value buckets
__device__ float g_scores[SCORES_ELEMS];   // scores, then attn in-place
__device__ float g_ctx[MROWS * D_];        // [b][s][h*64+d]
__device__ unsigned g_flags;
__device__ int g_mask_mode;

// bf16 split-precision fragment images (mma.sync m16n8k16 register order)
__device__ uint32_t g_Ahi[MROWS * D_ / 2];   // 16MB
__device__ uint32_t g_Alo[MROWS * D_ / 2];   // 16MB
__device__ uint32_t g_Whi[D_ * D_ / 2];      // 2MB
__device__ uint32_t g_Wlo[D_ * D_ / 2];      // 2MB

// per-head fragment images for attention GEMMs ([bh] blocked)
static constexpr int HEADW = BH_ * S_ * DK_ / 2;   // 4.19M words each
__device__ uint32_t g_Qhi[HEADW];
__device__ uint32_t g_Qlo[HEADW];
__device__ uint32_t g_Khi[HEADW];
__device__ uint32_t g_Klo[HEADW];
__device__ uint32_t g_Vhi[HEADW];
__device__ uint32_t g_Vlo[HEADW];

// ---------------------------------------------------------------------------
// bf16 split helpers
// ---------------------------------------------------------------------------
__device__ __forceinline__ void split_pair(float x0, float x1,
                                           uint32_t& h, uint32_t& l) {
    __nv_bfloat16 h0 = __float2bfloat16(x0);
    __nv_bfloat16 h1 = __float2bfloat16(x1);
    __nv_bfloat16 l0 = __float2bfloat16(x0 - __bfloat162float(h0));
    __nv_bfloat16 l1 = __float2bfloat16(x1 - __bfloat162float(h1));
    h = (uint32_t)__bfloat16_as_ushort(h0) | ((uint32_t)__bfloat16_as_ushort(h1) << 16);
    l = (uint32_t)__bfloat16_as_ushort(l0) | ((uint32_t)__bfloat16_as_ushort(l1) << 16);
}

// mma.sync m16n8k16 bf16: C += A*B (A row-major 16x16, B col-major 16x8)
__device__ __forceinline__ void mma_bf16(float* c,
                                         uint32_t a0, uint32_t a1, uint32_t a2, uint32_t a3,
                                         uint32_t b0, uint32_t b1) {
    asm volatile(
        "mma.sync.aligned.m16n8k16.row.col.f32.bf16.bf16.f32 "
        "{%0,%1,%2,%3}, {%4,%5,%6,%7}, {%8,%9}, {%0,%1,%2,%3};"
        : "+f"(c[0]), "+f"(c[1]), "+f"(c[2]), "+f"(c[3])
        : "r"(a0), "r"(a1), "r"(a2), "r"(a3), "r"(b0), "r"(b1));
}

// ---------------------------------------------------------------------------
// Mask dtype detection (bool serialization is ambiguous: f32/u8/i32/bf16)
// ---------------------------------------------------------------------------
__global__ void k_reset_flags() { g_flags = 0u; }

__global__ void k_detect_mask(const unsigned* __restrict__ w, int n) {
    unsigned f = 0;
    for (int i = blockIdx.x * blockDim.x + threadIdx.x; i < n;
         i += gridDim.x * blockDim.x) {
        unsigned x = w[i];
        if (x == 0u) continue;
        if (x == 0x3F800000u) { f |= 1u; continue; }
        if ((x & ~0x01010101u) == 0u) { f |= (x == 1u) ? 16u : 2u; continue; }
        unsigned lo = x & 0xFFFFu, hi = x >> 16;
        if ((lo == 0u || lo == 0x3F80u) && (hi == 0u || hi == 0x3F80u)) f |= 4u;
        else f |= 8u;
    }
    if (f) atomicOr(&g_flags, f);
}

__global__ void k_finalize_mask() {
    unsigned fl = g_flags;
    int m;
    if      (fl & 4u) m = 3;
    else if (fl & 1u) m = 0;
    else if (fl & 2u) m = 1;
    else              m = 2;
    g_mask_mode = m;
}

__device__ __forceinline__ bool mask_at(const void* m, int mode, size_t idx) {
    if (mode == 0) return ((const float*)m)[idx] != 0.0f;
    if (mode == 1) return ((const unsigned char*)m)[idx] != 0;
    if (mode == 3) return ((const unsigned short*)m)[idx] != 0;
    return ((const int*)m)[idx] != 0;
}

// ---------------------------------------------------------------------------
// Pack A[8192,1024] fp32 -> hi/lo fragment images (projection GEMM operand).
// ---------------------------------------------------------------------------
__global__ __launch_bounds__(256) void k_pack_a(
    const float* __restrict__ src,
    uint32_t* __restrict__ hi, uint32_t* __restrict__ lo)
{
    int idx = blockIdx.x * 256 + threadIdx.x;
    int r    = idx & 3;
    int lane = (idx >> 2) & 31;
    int ks   = (idx >> 7) & 63;
    int mblk = idx >> 13;
    int row = mblk * 16 + (lane >> 2) + (r & 1) * 8;
    int col = ks * 16 + (lane & 3) * 2 + (r >> 1) * 8;
    float2 x = *(const float2*)(src + (size_t)row * 1024 + col);
    uint32_t h, l;
    split_pair(x.x, x.y, h, l);
    hi[idx] = h; lo[idx] = l;
}

// ---------------------------------------------------------------------------
// Pack W[1024k,1024n] fp32 -> hi/lo B fragment images (col-major operand).
// ---------------------------------------------------------------------------
__global__ __launch_bounds__(256) void k_pack_w(
    const float* __restrict__ W,
    uint32_t* __restrict__ hi, uint32_t* __restrict__ lo)
{
    int idx = blockIdx.x * 256 + threadIdx.x;
    int r    = idx & 3;
    int lane = (idx >> 2) & 31;
    int ks   = (idx >> 7) & 63;
    int n16  = idx >> 13;
    int n = n16 * 16 + (r >> 1) * 8 + (lane >> 2);
    int k = ks * 16 + (lane & 3) * 2 + (r & 1) * 8;
    float x0 = W[(size_t)k * 1024 + n];
    float x1 = W[(size_t)(k + 1) * 1024 + n];
    uint32_t h, l;
    split_pair(x0, x1, h, l);
    hi[idx] = h; lo[idx] = l;
}

// ---------------------------------------------------------------------------
// Per-head packs for attention GEMMs.
// Q as A-operand: qp[bh][s][64] -> [bh][mblk64][ks4][lane][4]
// ---------------------------------------------------------------------------
__global__ __launch_bounds__(256) void k_pack_qa(
    const float* __restrict__ qp,
    uint32_t* __restrict__ hi, uint32_t* __restrict__ lo)
{
    int idx = blockIdx.x * 256 + threadIdx.x;     // 4.19M words
    int r    = idx & 3;
    int lane = (idx >> 2) & 31;
    int ks   = (idx >> 7) & 3;
    int mblk = (idx >> 9) & 63;
    int bh   = idx >> 15;
    int row = mblk * 16 + (lane >> 2) + (r & 1) * 8;
    int col = ks * 16 + (lane & 3) * 2 + (r >> 1) * 8;
    float2 x = *(const float2*)(qp + (((size_t)bh << 10) + row) * 64 + col);
    uint32_t h, l;
    split_pair(x.x, x.y, h, l);
    hi[idx] = h; lo[idx] = l;
}

// K as B-operand: kp[bh][s][64], B[k=d][n=s] = kp[n][k] -> [bh][n16=64][ks4][lane][4]
__global__ __launch_bounds__(256) void k_pack_kb(
    const float* __restrict__ kp,
    uint32_t* __restrict__ hi, uint32_t* __restrict__ lo)
{
    int idx = blockIdx.x * 256 + threadIdx.x;
    int r    = idx & 3;
    int lane = (idx >> 2) & 31;
    int ks   = (idx >> 7) & 3;
    int n16  = (idx >> 9) & 63;
    int bh   = idx >> 15;
    int n = n16 * 16 + (r >> 1) * 8 + (lane >> 2);
    int k = ks * 16 + (lane & 3) * 2 + (r & 1) * 8;
    float2 x = *(const float2*)(kp + (((size_t)bh << 10) + n) * 64 + k);
    uint32_t h, l;
    split_pair(x.x, x.y, h, l);
    hi[idx] = h; lo[idx] = l;
}

// V as B-operand: vp[bh][s][64], B[k=s][n=d] = vp[k][n] -> [bh][n16=4][ks64][lane][4]
__global__ __launch_bounds__(256) void k_pack_vb(
    const float* __restrict__ vp,
    uint32_t* __restrict__ hi, uint32_t* __restrict__ lo)
{
    int idx = blockIdx.x * 256 + threadIdx.x;
    int r    = idx & 3;
    int lane = (idx >> 2) & 31;
    int ks   = (idx >> 7) & 63;
    int n16  = (idx >> 13) & 3;
    int bh   = idx >> 15;
    int n = n16 * 16 + (r >> 1) * 8 + (lane >> 2);
    int k = ks * 16 + (lane & 3) * 2 + (r & 1) * 8;
    float x0 = vp[(((size_t)bh << 10) + k) * 64 + n];
    float x1 = vp[(((size_t)bh << 10) + k + 1) * 64 + n];
    uint32_t h, l;
    split_pair(x0, x1, h, l);
    hi[idx] = h; lo[idx] = l;
}

// ---------------------------------------------------------------------------
// Tensor-core split-bf16 GEMM: C[8192,1024] = A @ W (+bias, epilogue layout)
// ---------------------------------------------------------------------------
template <int MODE>
__global__ __launch_bounds__(256) void k_mma_gemm(
    const uint4* __restrict__ Ahi, const uint4* __restrict__ Alo,
    const uint4* __restrict__ Bhi, const uint4* __restrict__ Blo,
    const float* __restrict__ bias, float scale, float* __restrict__ out)
{
    const int tid = threadIdx.x, lane = tid & 31, wid = tid >> 5;
    const int warp_m = wid & 1, warp_n = wid >> 1;
    const int ntile = blockIdx.x, mtile = blockIdx.y;
    const int mb0 = mtile * 8 + warp_m * 4;
    const int nb0 = ntile * 8 + warp_n * 2;

    float acc[4][4][4];
#pragma unroll
    for (int i = 0; i < 4; i++)
#pragma unroll
        for (int j = 0; j < 4; j++)
#pragma unroll
            for (int c = 0; c < 4; c++) acc[i][j][c] = 0.f;

    uint4 ah[2][4], al[2][4], bh[2][2], bl[2][2];

#pragma unroll
    for (int i = 0; i < 4; i++) {
        ah[0][i] = Ahi[((size_t)(mb0 + i) * 64 + 0) * 32 + lane];
        al[0][i] = Alo[((size_t)(mb0 + i) * 64 + 0) * 32 + lane];
    }
#pragma unroll
    for (int j = 0; j < 2; j++) {
        bh[0][j] = Bhi[((size_t)(nb0 + j) * 64 + 0) * 32 + lane];
        bl[0][j] = Blo[((size_t)(nb0 + j) * 64 + 0) * 32 + lane];
    }

#pragma unroll 2
    for (int ks = 0; ks < 64; ks++) {
        const int cb = ks & 1, nb = cb ^ 1;
        if (ks + 1 < 64) {
#pragma unroll
            for (int i = 0; i < 4; i++) {
                ah[nb][i] = Ahi[((size_t)(mb0 + i) * 64 + ks + 1) * 32 + lane];
                al[nb][i] = Alo[((size_t)(mb0 + i) * 64 + ks + 1) * 32 + lane];
            }
#pragma unroll
            for (int j = 0; j < 2; j++) {
                bh[nb][j] = Bhi[((size_t)(nb0 + j) * 64 + ks + 1) * 32 + lane];
                bl[nb][j] = Blo[((size_t)(nb0 + j) * 64 + ks + 1) * 32 + lane];
            }
        }
#pragma unroll
        for (int i = 0; i < 4; i++) {
            const uint4 A = ah[cb][i], L = al[cb][i];
#pragma unroll
            for (int j = 0; j < 2; j++) {
                const uint4 Bh = bh[cb][j], Bl = bl[cb][j];
                mma_bf16(acc[i][j * 2], A.x, A.y, A.z, A.w, Bh.x, Bh.y);
                mma_bf16(acc[i][j * 2], L.x, L.y, L.z, L.w, Bh.x, Bh.y);
                mma_bf16(acc[i][j * 2], A.x, A.y, A.z, A.w, Bl.x, Bl.y);
                mma_bf16(acc[i][j * 2 + 1], A.x, A.y, A.z, A.w, Bh.z, Bh.w);
                mma_bf16(acc[i][j * 2 + 1], L.x, L.y, L.z, L.w, Bh.z, Bh.w);
                mma_bf16(acc[i][j * 2 + 1], A.x, A.y, A.z, A.w, Bl.z, Bl.w);
            }
        }
    }

#pragma unroll
    for (int i = 0; i < 4; i++) {
        const int row0 = mtile * 128 + warp_m * 64 + i * 16 + (lane >> 2);
#pragma unroll
        for (int j = 0; j < 4; j++) {
            const int col0 = ntile * 128 + warp_n * 32 + j * 8 + (lane & 3) * 2;
            const float b0 = bias[col0], b1 = bias[col0 + 1];
#pragma unroll
            for (int half = 0; half < 2; half++) {
                const int row = row0 + half * 8;
                float v0 = acc[i][j][half * 2 + 0] + b0;
                float v1 = acc[i][j][half * 2 + 1] + b1;
                if (MODE == 0) {
                    v0 *= scale; v1 *= scale;
                    const int bb = row >> 10, ss = row & 1023;
                    const int hh = col0 >> 6, dk = col0 & 63;
                    float* dst = out + ((((size_t)(bb * 16 + hh)) << 10) + ss) * 64 + dk;
                    *(float2*)dst = make_float2(v0, v1);
                } else {
                    *(float2*)(out + (size_t)row * 1024 + col0) = make_float2(v0, v1);
                }
            }
        }
    }
}

// ---------------------------------------------------------------------------
// qrel[bhs][t] = sum_d qp[bhs][d] * rel_k[t][d]   (q already scaled)
// ---------------------------------------------------------------------------
__global__ __launch_bounds__(256) void k_qrel(const float* __restrict__ qp,
                                              const float* __restrict__ rel_k,
                                              float* __restrict__ qrel)
{
    __shared__ float rk[V_ * 65];
    __shared__ float qs[8 * DK_];
    const int tid = threadIdx.x;
    const long long r0 = (long long)blockIdx.x * 8;
    for (int i = tid; i < V_ * DK_; i += 256) {
        int t = i / DK_, d = i % DK_;
        rk[t * 65 + d] = rel_k[i];
    }
    for (int i = tid; i < 8 * DK_; i += 256) qs[i] = qp[r0 * DK_ + i];
    __syncthreads();
    const int wr = tid >> 5, lane = tid & 31;
    for (int t = lane; t < V_; t += 32) {
        float s = 0.f;
#pragma unroll
        for (int d = 0; d < DK_; d++) s += qs[wr * DK_ + d] * rk[t * 65 + d];
        qrel[(r0 + wr) * V_ + t] = s;
    }
}

// ---------------------------------------------------------------------------
// QK via mma: scores[bh][q][k] = Q.K^T + qrel gather, masked & adj-log folded
// grid (8 ktiles, 8 qtiles, 128 bh), 256 thr, warp tile 64x32, 4 ksteps.
// ---------------------------------------------------------------------------
__global__ __launch_bounds__(256) void k_qk_mma(
    const uint4* __restrict__ Qhi, const uint4* __restrict__ Qlo,
    const uint4* __restrict__ Khi, const uint4* __restrict__ Klo,
    const float* __restrict__ qrel, const void* __restrict__ mask,
    const float* __restrict__ adj, float* __restrict__ scores)
{
    const int tid = threadIdx.x, lane = tid & 31, wid = tid >> 5;
    const int warp_m = wid & 1, warp_n = wid >> 1;
    const int ktile = blockIdx.x, qtile = blockIdx.y, bh = blockIdx.z;
    const size_t base = (size_t)bh * 8192;   // uint4 per head image
    const int mb0 = qtile * 8 + warp_m * 4;  // 16-row units
    const int nb0 = ktile * 8 + warp_n * 2;  // 16-col units

    float acc[4][4][4];
#pragma unroll
    for (int i = 0; i < 4; i++)
#pragma unroll
        for (int j = 0; j < 4; j++)
#pragma unroll
            for (int c = 0; c < 4; c++) acc[i][j][c] = 0.f;

#pragma unroll
    for (int ks = 0; ks < 4; ks++) {
        uint4 ah[4], al[4], bhk[2], blk[2];
#pragma unroll
        for (int i = 0; i < 4; i++) {
            ah[i] = Qhi[base + (size_t)((mb0 + i) * 4 + ks) * 32 + lane];
            al[i] = Qlo[base + (size_t)((mb0 + i) * 4 + ks) * 32 + lane];
        }
#pragma unroll
        for (int j = 0; j < 2; j++) {
            bhk[j] = Khi[base + (size_t)((nb0 + j) * 4 + ks) * 32 + lane];
            blk[j] = Klo[base + (size_t)((nb0 + j) * 4 + ks) * 32 + lane];
        }
#pragma unroll
        for (int i = 0; i < 4; i++) {
            const uint4 A = ah[i], L = al[i];
#pragma unroll
            for (int j = 0; j < 2; j++) {
                const uint4 Bh = bhk[j], Bl = blk[j];
                mma_bf16(acc[i][j * 2], A.x, A.y, A.z, A.w, Bh.x, Bh.y);
                mma_bf16(acc[i][j * 2], L.x, L.y, L.z, L.w, Bh.x, Bh.y);
                mma_bf16(acc[i][j * 2], A.x, A.y, A.z, A.w, Bl.x, Bl.y);
                mma_bf16(acc[i][j * 2 + 1], A.x, A.y, A.z, A.w, Bh.z, Bh.w);
                mma_bf16(acc[i][j * 2 + 1], L.x, L.y, L.z, L.w, Bh.z, Bh.w);
                mma_bf16(acc[i][j * 2 + 1], A.x, A.y, A.z, A.w, Bl.z, Bl.w);
            }
        }
    }

    const int mode = g_mask_mode;
    const int bb = bh >> 4;
#pragma unroll
    for (int i = 0; i < 4; i++) {
        const int row0 = qtile * 128 + warp_m * 64 + i * 16 + (lane >> 2);
#pragma unroll
        for (int half = 0; half < 2; half++) {
            const int q = row0 + half * 8;
            const float* qr = qrel + ((size_t)bh * 1024 + q) * V_;
            const size_t mrow = ((size_t)bb * 1024 + q) << 10;
            const size_t arow = ((size_t)bh * 1024 + q) << 10;
#pragma unroll
            for (int j = 0; j < 4; j++) {
                const int col = ktile * 128 + warp_n * 32 + j * 8 + (lane & 3) * 2;
                float s0 = acc[i][j][half * 2 + 0];
                float s1 = acc[i][j][half * 2 + 1];
                int d0 = col - q;     d0 = d0 < -32 ? -32 : (d0 > 32 ? 32 : d0);
                int d1 = col + 1 - q; d1 = d1 < -32 ? -32 : (d1 > 32 ? 32 : d1);
                s0 += qr[d0 + 32];
                s1 += qr[d1 + 32];
                float2 av = *(const float2*)(adj + arow + col);
                bool m0 = mask_at(mask, mode, mrow + col);
                bool m1 = mask_at(mask, mode, mrow + col + 1);
                if (m0 || av.x == 0.0f) s0 = -1e30f;
                else if (av.x != 1.0f)  s0 -= __logf(av.x);
                if (m1 || av.y == 0.0f) s1 = -1e30f;
                else if (av.y != 1.0f)  s1 -= __logf(av.y);
                *(float2*)(scores + arow + col) = make_float2(s0, s1);
            }
        }
    }
}

// ---------------------------------------------------------------------------
// Softmax (warp per row) + rel-value buckets; attn written in-place + to d_out
// ---------------------------------------------------------------------------
__global__ __launch_bounds__(256) void k_softmax(float* __restrict__ scores,
                                                 float* __restrict__ wbuf,
                                                 float* __restrict__ attn_out)
{
    const int lane = threadIdx.x & 31;
    const long long row = (long long)blockIdx.x * 8 + (threadIdx.x >> 5);
    float* srow = scores + (size_t)row * S_;
    float4 v[8];
#pragma unroll
    for (int i = 0; i < 8; i++) v[i] = *(const float4*)(srow + i * 128 + lane * 4);

    float mx = -3.4e38f;
#pragma unroll
    for (int i = 0; i < 8; i++) {
        mx = fmaxf(mx, fmaxf(fmaxf(v[i].x, v[i].y), fmaxf(v[i].z, v[i].w)));
    }
#pragma unroll
    for (int o = 16; o; o >>= 1) mx = fmaxf(mx, __shfl_xor_sync(0xffffffffu, mx, o));

    float sum = 0.f;
#pragma unroll
    for (int i = 0; i < 8; i++) {
        v[i].x = __expf(v[i].x - mx); v[i].y = __expf(v[i].y - mx);
        v[i].z = __expf(v[i].z - mx); v[i].w = __expf(v[i].w - mx);
        sum += v[i].x + v[i].y + v[i].z + v[i].w;
    }
#pragma unroll
    for (int o = 16; o; o >>= 1) sum += __shfl_xor_sync(0xffffffffu, sum, o);
    float inv = sum > 0.f ? 1.f / sum : 0.f;

    const int q = (int)(row & 1023);
    float* wrow = wbuf + (size_t)row * V_;
    for (int t = lane; t < V_; t += 32) wrow[t] = 0.f;
    __syncwarp();

    float* arow = attn_out ? attn_out + (size_t)row * S_ : nullptr;
    float pre = 0.f, suf = 0.f;
#pragma unroll
    for (int i = 0; i < 8; i++) {
        int kb = i * 128 + lane * 4;
        v[i].x *= inv; v[i].y *= inv; v[i].z *= inv; v[i].w *= inv;
        float vals[4] = {v[i].x, v[i].y, v[i].z, v[i].w};
#pragma unroll
        for (int j = 0; j < 4; j++) {
            int k = kb + j;
            if (k <= q - 32)      pre += vals[j];
            else if (k >= q + 32) suf += vals[j];
            else                  wrow[k - q + 32] = vals[j];
        }
        *(float4*)(srow + kb) = v[i];
        if (arow) *(float4*)(arow + kb) = v[i];
    }
#pragma unroll
    for (int o = 16; o; o >>= 1) {
        pre += __shfl_xor_sync(0xffffffffu, pre, o);
        suf += __shfl_xor_sync(0xffffffffu, suf, o);
    }
    if (lane == 0) { wrow[0] = pre; wrow[64] = suf; }
}

// ---------------------------------------------------------------------------
// AV via mma: ctx[bh][q][d] = sum_k attn[q][k] * vp[k][d] -> [b][s][h*64+d]
// grid (8 mtiles, 128 bh), 256 thr; warp tile 16x64; attn split on the fly.
// ---------------------------------------------------------------------------
__global__ __launch_bounds__(256) void k_av_mma(
    const float* __restrict__ attn,
    const uint4* __restrict__ Vhi, const uint4* __restrict__ Vlo,
    float* __restrict__ ctx)
{
    const int tid = threadIdx.x, lane = tid & 31, wid = tid >> 5;
    const int mtile = blockIdx.x, bh = blockIdx.y;
    const size_t vb = (size_t)bh * 8192;    // uint4 per head image
    const int row0 = mtile * 128 + wid * 16 + (lane >> 2);
    const float* rowA = attn + ((size_t)bh * 1024 + row0) * 1024;
    const float* rowB = rowA + (size_t)8 * 1024;

    float acc[4][2][4];
#pragma unroll
    for (int nb = 0; nb < 4; nb++)
#pragma unroll
        for (int e = 0; e < 2; e++)
#pragma unroll
            for (int c = 0; c < 4; c++) acc[nb][e][c] = 0.f;

#pragma unroll 2
    for (int ks = 0; ks < 64; ks++) {
        const int k0 = ks * 16 + (lane & 3) * 2;
        float2 x0 = *(const float2*)(rowA + k0);
        float2 x1 = *(const float2*)(rowB + k0);
        float2 x2 = *(const float2*)(rowA + k0 + 8);
        float2 x3 = *(const float2*)(rowB + k0 + 8);
        uint32_t ah0, ah1, ah2, ah3, al0, al1, al2, al3;
        split_pair(x0.x, x0.y, ah0, al0);
        split_pair(x1.x, x1.y, ah1, al1);
        split_pair(x2.x, x2.y, ah2, al2);
        split_pair(x3.x, x3.y, ah3, al3);
#pragma unroll
        for (int nb = 0; nb < 4; nb++) {
            const uint4 Bh = Vhi[vb + (size_t)(nb * 64 + ks) * 32 + lane];
            const uint4 Bl = Vlo[vb + (size_t)(nb * 64 + ks) * 32 + lane];
            mma_bf16(acc[nb][0], ah0, ah1, ah2, ah3, Bh.x, Bh.y);
            mma_bf16(acc[nb][0], al0, al1, al2, al3, Bh.x, Bh.y);
            mma_bf16(acc[nb][0], ah0, ah1, ah2, ah3, Bl.x, Bl.y);
            mma_bf16(acc[nb][1], ah0, ah1, ah2, ah3, Bh.z, Bh.w);
            mma_bf16(acc[nb][1], al0, al1, al2, al3, Bh.z, Bh.w);
            mma_bf16(acc[nb][1], ah0, ah1, ah2, ah3, Bl.z, Bl.w);
        }
    }

    const int bb = bh >> 4, hh = bh & 15;
#pragma unroll
    for (int nb = 0; nb < 4; nb++)
#pragma unroll
        for (int e = 0; e < 2; e++) {
            const int d = nb * 16 + e * 8 + (lane & 3) * 2;
#pragma unroll
            for (int half = 0; half < 2; half++) {
                const int q = row0 + half * 8;
                float2 v = make_float2(acc[nb][e][half * 2 + 0],
                                       acc[nb][e][half * 2 + 1]);
                *(float2*)(ctx + (((size_t)bb << 10) + q) * 1024 + hh * 64 + d) = v;
            }
        }
}

// ---------------------------------------------------------------------------
// ctx += w @ rel_v   (65x64 per row)
// ---------------------------------------------------------------------------
__global__ __launch_bounds__(256) void k_relctx(const float* __restrict__ wbuf,
                                                const float* __restrict__ rel_v,
                                                float* __restrict__ ctx)
{
    __shared__ float rv[V_ * 64];
    __shared__ float ws[4][V_];
    const int tid = threadIdx.x;
    const long long r0 = (long long)blockIdx.x * 4;
    for (int i = tid; i < V_ * 64; i += 256) rv[i] = rel_v[i];
    for (int i = tid; i < 4 * V_; i += 256)
        ws[i / V_][i % V_] = wbuf[(r0 + i / V_) * V_ + i % V_];
    __syncthreads();
    const int rr = tid >> 6;
    const int d = tid & 63;
    float acc = 0.f;
#pragma unroll
    for (int t = 0; t < V_; t++) acc += ws[rr][t] * rv[t * 64 + d];
    long long r = r0 + rr;
    int bh = (int)(r >> 10), s = (int)(r & 1023);
    int bb = bh >> 4, hh = bh & 15;
    ctx[((size_t)(bb * S_ + s)) * D_ + hh * 64 + d] += acc;
}

// ---------------------------------------------------------------------------
// Launch
// ---------------------------------------------------------------------------
extern "C" void kernel_launch(void* const* d_in, const int* in_sizes, int n_in,
                              void* d_out, int out_size)
{
    const float* key   = (const float*)d_in[0];
    const float* value = (const float*)d_in[1];
    const float* query = (const float*)d_in[2];
    const void*  mask  = d_in[3];
    const float* adj   = (const float*)d_in[4];
    const float* Wq = (const float*)d_in[5];
    const float* bq = (const float*)d_in[6];
    const float* Wk = (const float*)d_in[7];
    const float* bk = (const float*)d_in[8];
    const float* Wv = (const float*)d_in[9];
    const float* bv = (const float*)d_in[10];
    const float* Wo = (const float*)d_in[11];
    const float* bo = (const float*)d_in[12];
    const float* rel_k = (const float*)d_in[13];
    const float* rel_v = (const float*)d_in[14];
    float* outF = (float*)d_out;

    float *qp, *kp, *vp, *qrel, *wb, *sc, *ctx;
    uint32_t *ahi, *alo, *whi, *wlo, *qhi, *qlo, *khi, *klo, *vhi, *vlo;
    cudaGetSymbolAddress((void**)&qp,   g_qp);
    cudaGetSymbolAddress((void**)&kp,   g_kp);
    cudaGetSymbolAddress((void**)&vp,   g_vp);
    cudaGetSymbolAddress((void**)&qrel, g_qrel);
    cudaGetSymbolAddress((void**)&wb,   g_w);
    cudaGetSymbolAddress((void**)&sc,   g_scores);
    cudaGetSymbolAddress((void**)&ctx,  g_ctx);
    cudaGetSymbolAddress((void**)&ahi,  g_Ahi);
    cudaGetSymbolAddress((void**)&alo,  g_Alo);
    cudaGetSymbolAddress((void**)&whi,  g_Whi);
    cudaGetSymbolAddress((void**)&wlo,  g_Wlo);
    cudaGetSymbolAddress((void**)&qhi,  g_Qhi);
    cudaGetSymbolAddress((void**)&qlo,  g_Qlo);
    cudaGetSymbolAddress((void**)&khi,  g_Khi);
    cudaGetSymbolAddress((void**)&klo,  g_Klo);
    cudaGetSymbolAddress((void**)&vhi,  g_Vhi);
    cudaGetSymbolAddress((void**)&vlo,  g_Vlo);

    // mask dtype detection
    k_reset_flags<<<1, 1>>>();
    k_detect_mask<<<256, 256>>>((const unsigned*)mask, in_sizes[3] / 4);
    k_finalize_mask<<<1, 1>>>();

    const int APACK_BLOCKS = MROWS * D_ / 2 / 256;   // 16384
    const int WPACK_BLOCKS = D_ * D_ / 2 / 256;      // 2048
    const int HPACK_BLOCKS = HEADW / 256;            // 16384
    dim3 gg(8, 64);   // (ntiles, mtiles)

    // Q projection (pre-scaled by 1/8 incl. bias)
    k_pack_w<<<WPACK_BLOCKS, 256>>>(Wq, whi, wlo);
    k_pack_a<<<APACK_BLOCKS, 256>>>(query, ahi, alo);
    k_mma_gemm<0><<<gg, 256>>>((const uint4*)ahi, (const uint4*)alo,
                               (const uint4*)whi, (const uint4*)wlo, bq, 0.125f, qp);

    // K projection
    k_pack_w<<<WPACK_BLOCKS, 256>>>(Wk, whi, wlo);
    k_pack_a<<<APACK_BLOCKS, 256>>>(key, ahi, alo);
    k_mma_gemm<0><<<gg, 256>>>((const uint4*)ahi, (const uint4*)alo,
                               (const uint4*)whi, (const uint4*)wlo, bk, 1.0f, kp);

    // V projection
    k_pack_w<<<WPACK_BLOCKS, 256>>>(Wv, whi, wlo);
    k_pack_a<<<APACK_BLOCKS, 256>>>(value, ahi, alo);
    k_mma_gemm<0><<<gg, 256>>>((const uint4*)ahi, (const uint4*)alo,
                               (const uint4*)whi, (const uint4*)wlo, bv, 1.0f, vp);

    // per-head fragment packs for attention GEMMs
    k_pack_qa<<<HPACK_BLOCKS, 256>>>(qp, qhi, qlo);
    k_pack_kb<<<HPACK_BLOCKS, 256>>>(kp, khi, klo);
    k_pack_vb<<<HPACK_BLOCKS, 256>>>(vp, vhi, vlo);

    // relative-key projection (rank-65 trick)
    k_qrel<<<NROW / 8, 256>>>(qp, rel_k, qrel);

    // scores via tensor cores + mask + adj fold
    dim3 qkg(8, 8, BH_);
    k_qk_mma<<<qkg, 256>>>((const uint4*)qhi, (const uint4*)qlo,
                           (const uint4*)khi, (const uint4*)klo,
                           qrel, mask, adj, sc);

    // softmax + buckets (+ attn output if the harness expects it)
    bool hasAttn = (size_t)out_size >= (size_t)FINAL_ELEMS + SCORES_ELEMS;
    float* attnOut = hasAttn ? outF + FINAL_ELEMS : nullptr;
    k_softmax<<<NROW / 8, 256>>>(sc, wb, attnOut);

    // context via tensor cores
    dim3 avg(8, BH_);
    k_av_mma<<<avg, 256>>>(sc, (const uint4*)vhi, (const uint4*)vlo, ctx);
    k_relctx<<<NROW / 4, 256>>>(wb, rel_v, ctx);

    // output projection (row-major epilogue)
    k_pack_w<<<WPACK_BLOCKS, 256>>>(Wo, whi, wlo);
    k_pack_a<<<APACK_BLOCKS, 256>>>(ctx, ahi, alo);
    k_mma_gemm<1><<<gg, 256>>>((const uint4*)ahi, (const uint4*)alo,
                               (const uint4*)whi, (const uint4*)wlo, bo, 1.0f, outF);
}

// round 10
// speedup vs baseline: 1.6525x; 1.0067x over previous
#include <cuda_runtime.h>
#include <cuda_bf16.h>
#include <cstdint>

// ---------------------------------------------------------------------------
// Problem constants
// ---------------------------------------------------------------------------
static constexpr int B_  = 8;
static constexpr int S_  = 1024;
static constexpr int D_  = 1024;
static constexpr int H_  = 16;
static constexpr int DK_ = 64;
static constexpr int V_  = 65;            // 2*MAXREL+1
static constexpr int BH_ = B_ * H_;       // 128
static constexpr int MROWS = B_ * S_;     // 8192
static constexpr int NROW  = BH_ * S_;    // 131072 (b,h,s) rows
static constexpr size_t SCORES_ELEMS = (size_t)BH_ * S_ * S_;  // 134217728
static constexpr int FINAL_ELEMS = MROWS * D_;                 // 8388608

// ---------------------------------------------------------------------------
// Device scratch (static — no allocation allowed)
// ---------------------------------------------------------------------------
__device__ float g_qp[BH_ * S_ * DK_];     // Q projection, [bh][s][d], pre-scaled 1/8
__device__ float g_kp[BH_ * S_ * DK_];
__device__ float g_vp[BH_ * S_ * DK_];
__device__ float g_qrel[NROW * V_];        // q . rel_k[t]
__device__ float g_w[NROW * V_];           // relative-value buckets
__device__ float g_scores[SCORES_ELEMS];   // folded scores
__device__ float g_ctx[MROWS * D_];        // [b][s][h*64+d]
__device__ float2 g_stats[NROW];           // per-row softmax (max, sum)
__device__ unsigned g_flags;
__device__ int g_mask_mode;

// bf16 split-precision fragment images (mma.sync m16n8k16 register order)
__device__ uint32_t g_Ahi[MROWS * D_ / 2];   // 16MB
__device__ uint32_t g_Alo[MROWS * D_ / 2];   // 16MB
__device__ uint32_t g_Whi[D_ * D_ / 2];      // 2MB
__device__ uint32_t g_Wlo[D_ * D_ / 2];      // 2MB

// per-head fragment images for K (QK B-operand) and V (AV B-operand)
static constexpr int HEADW = BH_ * S_ * DK_ / 2;   // 4.19M words each
__device__ uint32_t g_Khi[HEADW];
__device__ uint32_t g_Klo[HEADW];
__device__ uint32_t g_Vhi[HEADW];
__device__ uint32_t g_Vlo[HEADW];

// ---------------------------------------------------------------------------
// bf16 split helpers
// ---------------------------------------------------------------------------
__device__ __forceinline__ void split_pair(float x0, float x1,
                                           uint32_t& h, uint32_t& l) {
    __nv_bfloat16 h0 = __float2bfloat16(x0);
    __nv_bfloat16 h1 = __float2bfloat16(x1);
    __nv_bfloat16 l0 = __float2bfloat16(x0 - __bfloat162float(h0));
    __nv_bfloat16 l1 = __float2bfloat16(x1 - __bfloat162float(h1));
    h = (uint32_t)__bfloat16_as_ushort(h0) | ((uint32_t)__bfloat16_as_ushort(h1) << 16);
    l = (uint32_t)__bfloat16_as_ushort(l0) | ((uint32_t)__bfloat16_as_ushort(l1) << 16);
}

// mma.sync m16n8k16 bf16: C += A*B (A row-major 16x16, B col-major 16x8)
__device__ __forceinline__ void mma_bf16(float* c,
                                         uint32_t a0, uint32_t a1, uint32_t a2, uint32_t a3,
                                         uint32_t b0, uint32_t b1) {
    asm volatile(
        "mma.sync.aligned.m16n8k16.row.col.f32.bf16.bf16.f32 "
        "{%0,%1,%2,%3}, {%4,%5,%6,%7}, {%8,%9}, {%0,%1,%2,%3};"
        : "+f"(c[0]), "+f"(c[1]), "+f"(c[2]), "+f"(c[3])
        : "r"(a0), "r"(a1), "r"(a2), "r"(a3), "r"(b0), "r"(b1));
}

// ---------------------------------------------------------------------------
// Mask dtype detection (bool serialization is ambiguous: f32/u8/i32/bf16)
// ---------------------------------------------------------------------------
__global__ void k_reset_flags() { g_flags = 0u; }

__global__ void k_detect_mask(const unsigned* __restrict__ w, int n) {
    unsigned f = 0;
    for (int i = blockIdx.x * blockDim.x + threadIdx.x; i < n;
         i += gridDim.x * blockDim.x) {
        unsigned x = w[i];
        if (x == 0u) continue;
        if (x == 0x3F800000u) { f |= 1u; continue; }
        if ((x & ~0x01010101u) == 0u) { f |= (x == 1u) ? 16u : 2u; continue; }
        unsigned lo = x & 0xFFFFu, hi = x >> 16;
        if ((lo == 0u || lo == 0x3F80u) && (hi == 0u || hi == 0x3F80u)) f |= 4u;
        else f |= 8u;
    }
    if (f) atomicOr(&g_flags, f);
}

__global__ void k_finalize_mask() {
    unsigned fl = g_flags;
    int m;
    if      (fl & 4u) m = 3;
    else if (fl & 1u) m = 0;
    else if (fl & 2u) m = 1;
    else              m = 2;
    g_mask_mode = m;
}

__device__ __forceinline__ bool mask_at(const void* m, int mode, size_t idx) {
    if (mode == 0) return ((const float*)m)[idx] != 0.0f;
    if (mode == 1) return ((const unsigned char*)m)[idx] != 0;
    if (mode == 3) return ((const unsigned short*)m)[idx] != 0;
    return ((const int*)m)[idx] != 0;
}

// ---------------------------------------------------------------------------
// Pack A[8192,1024] fp32 -> hi/lo fragment images (projection GEMM operand).
// ---------------------------------------------------------------------------
__global__ __launch_bounds__(256) void k_pack_a(
    const float* __restrict__ src,
    uint32_t* __restrict__ hi, uint32_t* __restrict__ lo)
{
    int idx = blockIdx.x * 256 + threadIdx.x;
    int r    = idx & 3;
    int lane = (idx >> 2) & 31;
    int ks   = (idx >> 7) & 63;
    int mblk = idx >> 13;
    int row = mblk * 16 + (lane >> 2) + (r & 1) * 8;
    int col = ks * 16 + (lane & 3) * 2 + (r >> 1) * 8;
    float2 x = *(const float2*)(src + (size_t)row * 1024 + col);
    uint32_t h, l;
    split_pair(x.x, x.y, h, l);
    hi[idx] = h; lo[idx] = l;
}

// ---------------------------------------------------------------------------
// Pack W[1024k,1024n] fp32 -> hi/lo B fragment images (col-major operand).
// ---------------------------------------------------------------------------
__global__ __launch_bounds__(256) void k_pack_w(
    const float* __restrict__ W,
    uint32_t* __restrict__ hi, uint32_t* __restrict__ lo)
{
    int idx = blockIdx.x * 256 + threadIdx.x;
    int r    = idx & 3;
    int lane = (idx >> 2) & 31;
    int ks   = (idx >> 7) & 63;
    int n16  = idx >> 13;
    int n = n16 * 16 + (r >> 1) * 8 + (lane >> 2);
    int k = ks * 16 + (lane & 3) * 2 + (r & 1) * 8;
    float x0 = W[(size_t)k * 1024 + n];
    float x1 = W[(size_t)(k + 1) * 1024 + n];
    uint32_t h, l;
    split_pair(x0, x1, h, l);
    hi[idx] = h; lo[idx] = l;
}

// K as B-operand: kp[bh][s][64], B[k=d][n=s] = kp[n][k] -> [bh][n16=64][ks4][lane][4]
__global__ __launch_bounds__(256) void k_pack_kb(
    const float* __restrict__ kp,
    uint32_t* __restrict__ hi, uint32_t* __restrict__ lo)
{
    int idx = blockIdx.x * 256 + threadIdx.x;
    int r    = idx & 3;
    int lane = (idx >> 2) & 31;
    int ks   = (idx >> 7) & 3;
    int n16  = (idx >> 9) & 63;
    int bh   = idx >> 15;
    int n = n16 * 16 + (r >> 1) * 8 + (lane >> 2);
    int k = ks * 16 + (lane & 3) * 2 + (r & 1) * 8;
    float2 x = *(const float2*)(kp + (((size_t)bh << 10) + n) * 64 + k);
    uint32_t h, l;
    split_pair(x.x, x.y, h, l);
    hi[idx] = h; lo[idx] = l;
}

// V as B-operand: vp[bh][s][64], B[k=s][n=d] = vp[k][n] -> [bh][n16=4][ks64][lane][4]
__global__ __launch_bounds__(256) void k_pack_vb(
    const float* __restrict__ vp,
    uint32_t* __restrict__ hi, uint32_t* __restrict__ lo)
{
    int idx = blockIdx.x * 256 + threadIdx.x;
    int r    = idx & 3;
    int lane = (idx >> 2) & 31;
    int ks   = (idx >> 7) & 63;
    int n16  = (idx >> 13) & 3;
    int bh   = idx >> 15;
    int n = n16 * 16 + (r >> 1) * 8 + (lane >> 2);
    int k = ks * 16 + (lane & 3) * 2 + (r & 1) * 8;
    float x0 = vp[(((size_t)bh << 10) + k) * 64 + n];
    float x1 = vp[(((size_t)bh << 10) + k + 1) * 64 + n];
    uint32_t h, l;
    split_pair(x0, x1, h, l);
    hi[idx] = h; lo[idx] = l;
}

// ---------------------------------------------------------------------------
// Tensor-core split-bf16 GEMM: C[8192,1024] = A @ W (+bias, epilogue layout)
// ---------------------------------------------------------------------------
template <int MODE>
__global__ __launch_bounds__(256) void k_mma_gemm(
    const uint4* __restrict__ Ahi, const uint4* __restrict__ Alo,
    const uint4* __restrict__ Bhi, const uint4* __restrict__ Blo,
    const float* __restrict__ bias, float scale, float* __restrict__ out)
{
    const int tid = threadIdx.x, lane = tid & 31, wid = tid >> 5;
    const int warp_m = wid & 1, warp_n = wid >> 1;
    const int ntile = blockIdx.x, mtile = blockIdx.y;
    const int mb0 = mtile * 8 + warp_m * 4;
    const int nb0 = ntile * 8 + warp_n * 2;

    float acc[4][4][4];
#pragma unroll
    for (int i = 0; i < 4; i++)
#pragma unroll
        for (int j = 0; j < 4; j++)
#pragma unroll
            for (int c = 0; c < 4; c++) acc[i][j][c] = 0.f;

    uint4 ah[2][4], al[2][4], bh[2][2], bl[2][2];

#pragma unroll
    for (int i = 0; i < 4; i++) {
        ah[0][i] = Ahi[((size_t)(mb0 + i) * 64 + 0) * 32 + lane];
        al[0][i] = Alo[((size_t)(mb0 + i) * 64 + 0) * 32 + lane];
    }
#pragma unroll
    for (int j = 0; j < 2; j++) {
        bh[0][j] = Bhi[((size_t)(nb0 + j) * 64 + 0) * 32 + lane];
        bl[0][j] = Blo[((size_t)(nb0 + j) * 64 + 0) * 32 + lane];
    }

#pragma unroll 2
    for (int ks = 0; ks < 64; ks++) {
        const int cb = ks & 1, nb = cb ^ 1;
        if (ks + 1 < 64) {
#pragma unroll
            for (int i = 0; i < 4; i++) {
                ah[nb][i] = Ahi[((size_t)(mb0 + i) * 64 + ks + 1) * 32 + lane];
                al[nb][i] = Alo[((size_t)(mb0 + i) * 64 + ks + 1) * 32 + lane];
            }
#pragma unroll
            for (int j = 0; j < 2; j++) {
                bh[nb][j] = Bhi[((size_t)(nb0 + j) * 64 + ks + 1) * 32 + lane];
                bl[nb][j] = Blo[((size_t)(nb0 + j) * 64 + ks + 1) * 32 + lane];
            }
        }
#pragma unroll
        for (int i = 0; i < 4; i++) {
            const uint4 A = ah[cb][i], L = al[cb][i];
#pragma unroll
            for (int j = 0; j < 2; j++) {
                const uint4 Bh = bh[cb][j], Bl = bl[cb][j];
                mma_bf16(acc[i][j * 2], A.x, A.y, A.z, A.w, Bh.x, Bh.y);
                mma_bf16(acc[i][j * 2], L.x, L.y, L.z, L.w, Bh.x, Bh.y);
                mma_bf16(acc[i][j * 2], A.x, A.y, A.z, A.w, Bl.x, Bl.y);
                mma_bf16(acc[i][j * 2 + 1], A.x, A.y, A.z, A.w, Bh.z, Bh.w);
                mma_bf16(acc[i][j * 2 + 1], L.x, L.y, L.z, L.w, Bh.z, Bh.w);
                mma_bf16(acc[i][j * 2 + 1], A.x, A.y, A.z, A.w, Bl.z, Bl.w);
            }
        }
    }

#pragma unroll
    for (int i = 0; i < 4; i++) {
        const int row0 = mtile * 128 + warp_m * 64 + i * 16 + (lane >> 2);
#pragma unroll
        for (int j = 0; j < 4; j++) {
            const int col0 = ntile * 128 + warp_n * 32 + j * 8 + (lane & 3) * 2;
            const float b0 = bias[col0], b1 = bias[col0 + 1];
#pragma unroll
            for (int half = 0; half < 2; half++) {
                const int row = row0 + half * 8;
                float v0 = acc[i][j][half * 2 + 0] + b0;
                float v1 = acc[i][j][half * 2 + 1] + b1;
                if (MODE == 0) {
                    v0 *= scale; v1 *= scale;
                    const int bb = row >> 10, ss = row & 1023;
                    const int hh = col0 >> 6, dk = col0 & 63;
                    float* dst = out + ((((size_t)(bb * 16 + hh)) << 10) + ss) * 64 + dk;
                    *(float2*)dst = make_float2(v0, v1);
                } else {
                    *(float2*)(out + (size_t)row * 1024 + col0) = make_float2(v0, v1);
                }
            }
        }
    }
}

// ---------------------------------------------------------------------------
// qrel[bhs][t] = sum_d qp[bhs][d] * rel_k[t][d]   (q already scaled)
// ---------------------------------------------------------------------------
__global__ __launch_bounds__(256) void k_qrel(const float* __restrict__ qp,
                                              const float* __restrict__ rel_k,
                                              float* __restrict__ qrel)
{
    __shared__ float rk[V_ * 65];
    __shared__ float qs[8 * DK_];
    const int tid = threadIdx.x;
    const long long r0 = (long long)blockIdx.x * 8;
    for (int i = tid; i < V_ * DK_; i += 256) {
        int t = i / DK_, d = i % DK_;
        rk[t * 65 + d] = rel_k[i];
    }
    for (int i = tid; i < 8 * DK_; i += 256) qs[i] = qp[r0 * DK_ + i];
    __syncthreads();
    const int wr = tid >> 5, lane = tid & 31;
    for (int t = lane; t < V_; t += 32) {
        float s = 0.f;
#pragma unroll
        for (int d = 0; d < DK_; d++) s += qs[wr * DK_ + d] * rk[t * 65 + d];
        qrel[(r0 + wr) * V_ + t] = s;
    }
}

// ---------------------------------------------------------------------------
// Pass A: QK mma + fold + scores store + online softmax row stats.
// grid (8 qtiles, 128 bh), 256 thr; warp = 16 q rows x all 1024 k.
// ---------------------------------------------------------------------------
__global__ __launch_bounds__(256) void k_qk_stats(
    const float* __restrict__ qp,
    const uint4* __restrict__ Khi, const uint4* __restrict__ Klo,
    const float* __restrict__ qrel, const void* __restrict__ mask,
    const float* __restrict__ adj, float* __restrict__ scores,
    float2* __restrict__ stats)
{
    const int tid = threadIdx.x, lane = tid & 31, wid = tid >> 5;
    const int qtile = blockIdx.x, bh = blockIdx.y;
    const int row0 = qtile * 128 + wid * 16 + (lane >> 2);
    const int row1 = row0 + 8;
    const size_t qbase = ((size_t)bh << 10);

    // Q fragments directly from qp (split on the fly, reused for all k)
    uint32_t qh[4][4], ql[4][4];
#pragma unroll
    for (int ks = 0; ks < 4; ks++) {
        const int c0 = ks * 16 + (lane & 3) * 2;
        float2 x0 = *(const float2*)(qp + (qbase + row0) * 64 + c0);
        float2 x1 = *(const float2*)(qp + (qbase + row1) * 64 + c0);
        float2 x2 = *(const float2*)(qp + (qbase + row0) * 64 + c0 + 8);
        float2 x3 = *(const float2*)(qp + (qbase + row1) * 64 + c0 + 8);
        split_pair(x0.x, x0.y, qh[ks][0], ql[ks][0]);
        split_pair(x1.x, x1.y, qh[ks][1], ql[ks][1]);
        split_pair(x2.x, x2.y, qh[ks][2], ql[ks][2]);
        split_pair(x3.x, x3.y, qh[ks][3], ql[ks][3]);
    }

    const int mode = g_mask_mode;
    const int bb = bh >> 4;
    const float* qr0 = qrel + (qbase + row0) * V_;
    const float* qr1 = qrel + (qbase + row1) * V_;
    const size_t arow0 = (qbase + row0) << 10;
    const size_t arow1 = (qbase + row1) << 10;
    const size_t mrow0 = (((size_t)bb << 10) + row0) << 10;
    const size_t mrow1 = (((size_t)bb << 10) + row1) << 10;
    const size_t kb = (size_t)bh * 8192;   // uint4 per head K image

    float m0 = -3.4e38f, m1 = -3.4e38f, s0 = 0.f, s1 = 0.f;

    for (int kt = 0; kt < 16; kt++) {      // 64-col tiles
        float acc[8][4];
#pragma unroll
        for (int p = 0; p < 8; p++)
#pragma unroll
            for (int c = 0; c < 4; c++) acc[p][c] = 0.f;

#pragma unroll
        for (int ks = 0; ks < 4; ks++) {
#pragma unroll
            for (int b = 0; b < 4; b++) {
                const int n16 = kt * 4 + b;
                const uint4 Bh = Khi[kb + (size_t)(n16 * 4 + ks) * 32 + lane];
                const uint4 Bl = Klo[kb + (size_t)(n16 * 4 + ks) * 32 + lane];
                mma_bf16(acc[b*2],   qh[ks][0], qh[ks][1], qh[ks][2], qh[ks][3], Bh.x, Bh.y);
                mma_bf16(acc[b*2],   ql[ks][0], ql[ks][1], ql[ks][2], ql[ks][3], Bh.x, Bh.y);
                mma_bf16(acc[b*2],   qh[ks][0], qh[ks][1], qh[ks][2], qh[ks][3], Bl.x, Bl.y);
                mma_bf16(acc[b*2+1], qh[ks][0], qh[ks][1], qh[ks][2], qh[ks][3], Bh.z, Bh.w);
                mma_bf16(acc[b*2+1], ql[ks][0], ql[ks][1], ql[ks][2], ql[ks][3], Bh.z, Bh.w);
                mma_bf16(acc[b*2+1], qh[ks][0], qh[ks][1], qh[ks][2], qh[ks][3], Bl.z, Bl.w);
            }
        }

        float tm0 = -3.4e38f, tm1 = -3.4e38f;
#pragma unroll
        for (int p = 0; p < 8; p++) {
            const int col = kt * 64 + p * 8 + (lane & 3) * 2;
            // row0 pair
            {
                float v0 = acc[p][0], v1 = acc[p][1];
                int d0 = col - row0;     d0 = d0 < -32 ? -32 : (d0 > 32 ? 32 : d0);
                int d1 = col + 1 - row0; d1 = d1 < -32 ? -32 : (d1 > 32 ? 32 : d1);
                v0 += qr0[d0 + 32];
                v1 += qr0[d1 + 32];
                float2 av = *(const float2*)(adj + arow0 + col);
                if (mask_at(mask, mode, mrow0 + col)     || av.x == 0.0f) v0 = -1e30f;
                else if (av.x != 1.0f) v0 -= __logf(av.x);
                if (mask_at(mask, mode, mrow0 + col + 1) || av.y == 0.0f) v1 = -1e30f;
                else if (av.y != 1.0f) v1 -= __logf(av.y);
                *(float2*)(scores + arow0 + col) = make_float2(v0, v1);
                tm0 = fmaxf(tm0, fmaxf(v0, v1));
                acc[p][0] = v0; acc[p][1] = v1;
            }
            // row1 pair
            {
                float v0 = acc[p][2], v1 = acc[p][3];
                int d0 = col - row1;     d0 = d0 < -32 ? -32 : (d0 > 32 ? 32 : d0);
                int d1 = col + 1 - row1; d1 = d1 < -32 ? -32 : (d1 > 32 ? 32 : d1);
                v0 += qr1[d0 + 32];
                v1 += qr1[d1 + 32];
                float2 av = *(const float2*)(adj + arow1 + col);
                if (mask_at(mask, mode, mrow1 + col)     || av.x == 0.0f) v0 = -1e30f;
                else if (av.x != 1.0f) v0 -= __logf(av.x);
                if (mask_at(mask, mode, mrow1 + col + 1) || av.y == 0.0f) v1 = -1e30f;
                else if (av.y != 1.0f) v1 -= __logf(av.y);
                *(float2*)(scores + arow1 + col) = make_float2(v0, v1);
                tm1 = fmaxf(tm1, fmaxf(v0, v1));
                acc[p][2] = v0; acc[p][3] = v1;
            }
        }
        // online (max, sum) update
        const float nm0 = fmaxf(m0, tm0);
        const float nm1 = fmaxf(m1, tm1);
        s0 *= __expf(m0 - nm0);
        s1 *= __expf(m1 - nm1);
#pragma unroll
        for (int p = 0; p < 8; p++) {
            s0 += __expf(acc[p][0] - nm0) + __expf(acc[p][1] - nm0);
            s1 += __expf(acc[p][2] - nm1) + __expf(acc[p][3] - nm1);
        }
        m0 = nm0; m1 = nm1;
    }

    // combine across the 4 lanes sharing each row
#pragma unroll
    for (int o = 1; o <= 2; o <<= 1) {
        float om = __shfl_xor_sync(0xffffffffu, m0, o);
        float os = __shfl_xor_sync(0xffffffffu, s0, o);
        float nm = fmaxf(m0, om);
        s0 = s0 * __expf(m0 - nm) + os * __expf(om - nm); m0 = nm;
        om = __shfl_xor_sync(0xffffffffu, m1, o);
        os = __shfl_xor_sync(0xffffffffu, s1, o);
        nm = fmaxf(m1, om);
        s1 = s1 * __expf(m1 - nm) + os * __expf(om - nm); m1 = nm;
    }
    if ((lane & 3) == 0) {
        stats[qbase + row0] = make_float2(m0, s0);
        stats[qbase + row1] = make_float2(m1, s1);
    }
}

// ---------------------------------------------------------------------------
// Pass B: read scores, p = exp(s-mx)*inv, write attn to d_out, rel-value
// buckets, and AV via mma with p repacked in-register as A fragments.
// grid (8 qtiles, 128 bh), 256 thr; warp = 16 q rows.
// ---------------------------------------------------------------------------
__global__ __launch_bounds__(256) void k_av_fused(
    const float* __restrict__ scores,
    const uint4* __restrict__ Vhi, const uint4* __restrict__ Vlo,
    const float2* __restrict__ stats, float* __restrict__ wbuf,
    float* __restrict__ attn_out, float* __restrict__ ctx)
{
    const int tid = threadIdx.x, lane = tid & 31, wid = tid >> 5;
    const int qtile = blockIdx.x, bh = blockIdx.y;
    const int row0 = qtile * 128 + wid * 16 + (lane >> 2);
    const int row1 = row0 + 8;
    const size_t grow0 = ((size_t)bh << 10) + row0;

    const float2 st0 = stats[grow0];
    const float2 st1 = stats[grow0 + 8];
    const float mx0 = st0.x, inv0 = st0.y > 0.f ? 1.f / st0.y : 0.f;
    const float mx1 = st1.x, inv1 = st1.y > 0.f ? 1.f / st1.y : 0.f;

    // zero this warp's 16 wbuf rows
    const size_t wrbase = ((size_t)bh << 10) + qtile * 128 + wid * 16;
    for (int i = lane; i < 16 * V_; i += 32) wbuf[wrbase * V_ + i] = 0.f;
    __syncwarp();

    float cacc[4][2][4];
#pragma unroll
    for (int nb = 0; nb < 4; nb++)
#pragma unroll
        for (int e = 0; e < 2; e++)
#pragma unroll
            for (int c = 0; c < 4; c++) cacc[nb][e][c] = 0.f;

    float pre0 = 0.f, suf0 = 0.f, pre1 = 0.f, suf1 = 0.f;
    const float* s0p = scores + (grow0 << 10);
    const float* s1p = s0p + (size_t)8 * 1024;
    float* a0p = attn_out ? attn_out + (grow0 << 10) : nullptr;
    float* wr0 = wbuf + grow0 * V_;
    float* wr1 = wr0 + (size_t)8 * V_;
    const size_t vb = (size_t)bh * 8192;

#pragma unroll 2
    for (int kstep = 0; kstep < 64; kstep++) {
        const int col = kstep * 16 + (lane & 3) * 2;
        float2 v00 = *(const float2*)(s0p + col);
        float2 v01 = *(const float2*)(s0p + col + 8);
        float2 v10 = *(const float2*)(s1p + col);
        float2 v11 = *(const float2*)(s1p + col + 8);
        v00.x = __expf(v00.x - mx0) * inv0; v00.y = __expf(v00.y - mx0) * inv0;
        v01.x = __expf(v01.x - mx0) * inv0; v01.y = __expf(v01.y - mx0) * inv0;
        v10.x = __expf(v10.x - mx1) * inv1; v10.y = __expf(v10.y - mx1) * inv1;
        v11.x = __expf(v11.x - mx1) * inv1; v11.y = __expf(v11.y - mx1) * inv1;
        if (a0p) {
            *(float2*)(a0p + col)              = v00;
            *(float2*)(a0p + col + 8)          = v01;
            *(float2*)(a0p + 8 * 1024 + col)     = v10;
            *(float2*)(a0p + 8 * 1024 + col + 8) = v11;
        }
        // rel-value buckets
        {
            float pv[4] = {v00.x, v00.y, v01.x, v01.y};
            int   kc[4] = {col, col + 1, col + 8, col + 9};
#pragma unroll
            for (int e = 0; e < 4; e++) {
                int d = kc[e] - row0;
                if (d <= -32)      pre0 += pv[e];
                else if (d >= 32)  suf0 += pv[e];
                else               wr0[d + 32] = pv[e];
            }
            float qv[4] = {v10.x, v10.y, v11.x, v11.y};
#pragma unroll
            for (int e = 0; e < 4; e++) {
                int d = kc[e] - row1;
                if (d <= -32)      pre1 += qv[e];
                else if (d >= 32)  suf1 += qv[e];
                else               wr1[d + 32] = qv[e];
            }
        }
        // repack p as A fragments (QK acc layout == AV A-frag layout)
        uint32_t ah0, ah1, ah2, ah3, al0, al1, al2, al3;
        split_pair(v00.x, v00.y, ah0, al0);
        split_pair(v10.x, v10.y, ah1, al1);
        split_pair(v01.x, v01.y, ah2, al2);
        split_pair(v11.x, v11.y, ah3, al3);
#pragma unroll
        for (int nb = 0; nb < 4; nb++) {
            const uint4 Bh = Vhi[vb + (size_t)(nb * 64 + kstep) * 32 + lane];
            const uint4 Bl = Vlo[vb + (size_t)(nb * 64 + kstep) * 32 + lane];
            mma_bf16(cacc[nb][0], ah0, ah1, ah2, ah3, Bh.x, Bh.y);
            mma_bf16(cacc[nb][0], al0, al1, al2, al3, Bh.x, Bh.y);
            mma_bf16(cacc[nb][0], ah0, ah1, ah2, ah3, Bl.x, Bl.y);
            mma_bf16(cacc[nb][1], ah0, ah1, ah2, ah3, Bh.z, Bh.w);
            mma_bf16(cacc[nb][1], al0, al1, al2, al3, Bh.z, Bh.w);
            mma_bf16(cacc[nb][1], ah0, ah1, ah2, ah3, Bl.z, Bl.w);
        }
    }

    // reduce pre/suf across the 4 lanes per row, write bucket endpoints
#pragma unroll
    for (int o = 1; o <= 2; o <<= 1) {
        pre0 += __shfl_xor_sync(0xffffffffu, pre0, o);
        suf0 += __shfl_xor_sync(0xffffffffu, suf0, o);
        pre1 += __shfl_xor_sync(0xffffffffu, pre1, o);
        suf1 += __shfl_xor_sync(0xffffffffu, suf1, o);
    }
    if ((lane & 3) == 0) {
        wr0[0] = pre0; wr0[64] = suf0;
        wr1[0] = pre1; wr1[64] = suf1;
    }

    // ctx write [b][s][h*64+d]
    const int bb = bh >> 4, hh = bh & 15;
#pragma unroll
    for (int nb = 0; nb < 4; nb++)
#pragma unroll
        for (int e = 0; e < 2; e++) {
            const int d = nb * 16 + e * 8 + (lane & 3) * 2;
#pragma unroll
            for (int half = 0; half < 2; half++) {
                const int q = row0 + half * 8;
                float2 v = make_float2(cacc[nb][e][half * 2 + 0],
                                       cacc[nb][e][half * 2 + 1]);
                *(float2*)(ctx + (((size_t)bb << 10) + q) * 1024 + hh * 64 + d) = v;
            }
        }
}

// ---------------------------------------------------------------------------
// ctx += w @ rel_v   (65x64 per row)
// ---------------------------------------------------------------------------
__global__ __launch_bounds__(256) void k_relctx(const float* __restrict__ wbuf,
                                                const float* __restrict__ rel_v,
                                                float* __restrict__ ctx)
{
    __shared__ float rv[V_ * 64];
    __shared__ float ws[4][V_];
    const int tid = threadIdx.x;
    const long long r0 = (long long)blockIdx.x * 4;
    for (int i = tid; i < V_ * 64; i += 256) rv[i] = rel_v[i];
    for (int i = tid; i < 4 * V_; i += 256)
        ws[i / V_][i % V_] = wbuf[(r0 + i / V_) * V_ + i % V_];
    __syncthreads();
    const int rr = tid >> 6;
    const int d = tid & 63;
    float acc = 0.f;
#pragma unroll
    for (int t = 0; t < V_; t++) acc += ws[rr][t] * rv[t * 64 + d];
    long long r = r0 + rr;
    int bh = (int)(r >> 10), s = (int)(r & 1023);
    int bb = bh >> 4, hh = bh & 15;
    ctx[((size_t)(bb * S_ + s)) * D_ + hh * 64 + d] += acc;
}

// ---------------------------------------------------------------------------
// Launch
// ---------------------------------------------------------------------------
extern "C" void kernel_launch(void* const* d_in, const int* in_sizes, int n_in,
                              void* d_out, int out_size)
{
    const float* key   = (const float*)d_in[0];
    const float* value = (const float*)d_in[1];
    const float* query = (const float*)d_in[2];
    const void*  mask  = d_in[3];
    const float* adj   = (const float*)d_in[4];
    const float* Wq = (const float*)d_in[5];
    const float* bq = (const float*)d_in[6];
    const float* Wk = (const float*)d_in[7];
    const float* bk = (const float*)d_in[8];
    const float* Wv = (const float*)d_in[9];
    const float* bv = (const float*)d_in[10];
    const float* Wo = (const float*)d_in[11];
    const float* bo = (const float*)d_in[12];
    const float* rel_k = (const float*)d_in[13];
    const float* rel_v = (const float*)d_in[14];
    float* outF = (float*)d_out;

    float *qp, *kp, *vp, *qrel, *wb, *sc, *ctx;
    float2* stats;
    uint32_t *ahi, *alo, *whi, *wlo, *khi, *klo, *vhi, *vlo;
    cudaGetSymbolAddress((void**)&qp,    g_qp);
    cudaGetSymbolAddress((void**)&kp,    g_kp);
    cudaGetSymbolAddress((void**)&vp,    g_vp);
    cudaGetSymbolAddress((void**)&qrel,  g_qrel);
    cudaGetSymbolAddress((void**)&wb,    g_w);
    cudaGetSymbolAddress((void**)&sc,    g_scores);
    cudaGetSymbolAddress((void**)&ctx,   g_ctx);
    cudaGetSymbolAddress((void**)&stats, g_stats);
    cudaGetSymbolAddress((void**)&ahi,   g_Ahi);
    cudaGetSymbolAddress((void**)&alo,   g_Alo);
    cudaGetSymbolAddress((void**)&whi,   g_Whi);
    cudaGetSymbolAddress((void**)&wlo,   g_Wlo);
    cudaGetSymbolAddress((void**)&khi,   g_Khi);
    cudaGetSymbolAddress((void**)&klo,   g_Klo);
    cudaGetSymbolAddress((void**)&vhi,   g_Vhi);
    cudaGetSymbolAddress((void**)&vlo,   g_Vlo);

    // mask dtype detection
    k_reset_flags<<<1, 1>>>();
    k_detect_mask<<<256, 256>>>((const unsigned*)mask, in_sizes[3] / 4);
    k_finalize_mask<<<1, 1>>>();

    const int APACK_BLOCKS = MROWS * D_ / 2 / 256;   // 16384
    const int WPACK_BLOCKS = D_ * D_ / 2 / 256;      // 2048
    const int HPACK_BLOCKS = HEADW / 256;            // 16384
    dim3 gg(8, 64);   // (ntiles, mtiles)

    // Q projection (pre-scaled by 1/8 incl. bias)
    k_pack_w<<<WPACK_BLOCKS, 256>>>(Wq, whi, wlo);
    k_pack_a<<<APACK_BLOCKS, 256>>>(query, ahi, alo);
    k_mma_gemm<0><<<gg, 256>>>((const uint4*)ahi, (const uint4*)alo,
                               (const uint4*)whi, (const uint4*)wlo, bq, 0.125f, qp);

    // K projection
    k_pack_w<<<WPACK_BLOCKS, 256>>>(Wk, whi, wlo);
    k_pack_a<<<APACK_BLOCKS, 256>>>(key, ahi, alo);
    k_mma_gemm<0><<<gg, 256>>>((const uint4*)ahi, (const uint4*)alo,
                               (const uint4*)whi, (const uint4*)wlo, bk, 1.0f, kp);

    // V projection
    k_pack_w<<<WPACK_BLOCKS, 256>>>(Wv, whi, wlo);
    k_pack_a<<<APACK_BLOCKS, 256>>>(value, ahi, alo);
    k_mma_gemm<0><<<gg, 256>>>((const uint4*)ahi, (const uint4*)alo,
                               (const uint4*)whi, (const uint4*)wlo, bv, 1.0f, vp);

    // per-head fragment packs (K for QK, V for AV)
    k_pack_kb<<<HPACK_BLOCKS, 256>>>(kp, khi, klo);
    k_pack_vb<<<HPACK_BLOCKS, 256>>>(vp, vhi, vlo);

    // relative-key projection (rank-65 trick)
    k_qrel<<<NROW / 8, 256>>>(qp, rel_k, qrel);

    // Pass A: scores + fold + row stats
    dim3 ag(8, BH_);
    k_qk_stats<<<ag, 256>>>(qp, (const uint4*)khi, (const uint4*)klo,
                            qrel, mask, adj, sc, stats);

    // Pass B: normalize + attn out + buckets + AV
    bool hasAttn = (size_t)out_size >= (size_t)FINAL_ELEMS + SCORES_ELEMS;
    float* attnOut = hasAttn ? outF + FINAL_ELEMS : nullptr;
    k_av_fused<<<ag, 256>>>(sc, (const uint4*)vhi, (const uint4*)vlo,
                            stats, wb, attnOut, ctx);

    k_relctx<<<NROW / 4, 256>>>(wb, rel_v, ctx);

    // output projection (row-major epilogue)
    k_pack_w<<<WPACK_BLOCKS, 256>>>(Wo, whi, wlo);
    k_pack_a<<<APACK_BLOCKS, 256>>>(ctx, ahi, alo);
    k_mma_gemm<1><<<gg, 256>>>((const uint4*)ahi, (const uint4*)alo,
                               (const uint4*)whi, (const uint4*)wlo, bo, 1.0f, outF);
}

// round 11
// speedup vs baseline: 1.6905x; 1.0230x over previous
#include <cuda_runtime.h>
#include <cuda_bf16.h>
#include <cstdint>

// ---------------------------------------------------------------------------
// Problem constants
// ---------------------------------------------------------------------------
static constexpr int B_  = 8;
static constexpr int S_  = 1024;
static constexpr int D_  = 1024;
static constexpr int H_  = 16;
static constexpr int DK_ = 64;
static constexpr int V_  = 65;            // 2*MAXREL+1
static constexpr int BH_ = B_ * H_;       // 128
static constexpr int MROWS = B_ * S_;     // 8192
static constexpr int NROW  = BH_ * S_;    // 131072 (b,h,s) rows
static constexpr size_t SCORES_ELEMS = (size_t)BH_ * S_ * S_;  // 134217728
static constexpr int FINAL_ELEMS = MROWS * D_;                 // 8388608

// ---------------------------------------------------------------------------
// Device scratch (static — no allocation allowed)
// ---------------------------------------------------------------------------
__device__ float g_qp[BH_ * S_ * DK_];     // Q projection, [bh][s][d], pre-scaled 1/8
__device__ float g_vp[BH_ * S_ * DK_];
__device__ float g_qrel[NROW * V_];        // q . rel_k[t]
__device__ float g_w[NROW * V_];           // relative-value buckets
__device__ float g_scores[SCORES_ELEMS];   // folded scores
__device__ float g_ctx[MROWS * D_];        // [b][s][h*64+d]
__device__ float2 g_stats[NROW];           // per-row softmax (max, sum)
__device__ unsigned g_flags;
__device__ int g_mask_mode;

// bf16 split-precision fragment images (mma.sync m16n8k16 register order)
__device__ uint32_t g_Ahi[MROWS * D_ / 2];   // 16MB
__device__ uint32_t g_Alo[MROWS * D_ / 2];   // 16MB
__device__ uint32_t g_Whi[D_ * D_ / 2];      // 2MB
__device__ uint32_t g_Wlo[D_ * D_ / 2];      // 2MB

// per-head fragment images for K (QK B-operand) and V (AV B-operand)
static constexpr int HEADW = BH_ * S_ * DK_ / 2;   // 4.19M words each
__device__ uint32_t g_Khi[HEADW];
__device__ uint32_t g_Klo[HEADW];
__device__ uint32_t g_Vhi[HEADW];
__device__ uint32_t g_Vlo[HEADW];

// ---------------------------------------------------------------------------
// bf16 split helpers
// ---------------------------------------------------------------------------
__device__ __forceinline__ void split_pair(float x0, float x1,
                                           uint32_t& h, uint32_t& l) {
    __nv_bfloat16 h0 = __float2bfloat16(x0);
    __nv_bfloat16 h1 = __float2bfloat16(x1);
    __nv_bfloat16 l0 = __float2bfloat16(x0 - __bfloat162float(h0));
    __nv_bfloat16 l1 = __float2bfloat16(x1 - __bfloat162float(h1));
    h = (uint32_t)__bfloat16_as_ushort(h0) | ((uint32_t)__bfloat16_as_ushort(h1) << 16);
    l = (uint32_t)__bfloat16_as_ushort(l0) | ((uint32_t)__bfloat16_as_ushort(l1) << 16);
}

// mma.sync m16n8k16 bf16: C += A*B (A row-major 16x16, B col-major 16x8)
__device__ __forceinline__ void mma_bf16(float* c,
                                         uint32_t a0, uint32_t a1, uint32_t a2, uint32_t a3,
                                         uint32_t b0, uint32_t b1) {
    asm volatile(
        "mma.sync.aligned.m16n8k16.row.col.f32.bf16.bf16.f32 "
        "{%0,%1,%2,%3}, {%4,%5,%6,%7}, {%8,%9}, {%0,%1,%2,%3};"
        : "+f"(c[0]), "+f"(c[1]), "+f"(c[2]), "+f"(c[3])
        : "r"(a0), "r"(a1), "r"(a2), "r"(a3), "r"(b0), "r"(b1));
}

// ---------------------------------------------------------------------------
// Mask dtype detection (bool serialization is ambiguous: f32/u8/i32/bf16)
// ---------------------------------------------------------------------------
__global__ void k_reset_flags() { g_flags = 0u; }

__global__ void k_detect_mask(const unsigned* __restrict__ w, int n) {
    unsigned f = 0;
    for (int i = blockIdx.x * blockDim.x + threadIdx.x; i < n;
         i += gridDim.x * blockDim.x) {
        unsigned x = w[i];
        if (x == 0u) continue;
        if (x == 0x3F800000u) { f |= 1u; continue; }
        if ((x & ~0x01010101u) == 0u) { f |= (x == 1u) ? 16u : 2u; continue; }
        unsigned lo = x & 0xFFFFu, hi = x >> 16;
        if ((lo == 0u || lo == 0x3F80u) && (hi == 0u || hi == 0x3F80u)) f |= 4u;
        else f |= 8u;
    }
    if (f) atomicOr(&g_flags, f);
}

__global__ void k_finalize_mask() {
    unsigned fl = g_flags;
    int m;
    if      (fl & 4u) m = 3;
    else if (fl & 1u) m = 0;
    else if (fl & 2u) m = 1;
    else              m = 2;
    g_mask_mode = m;
}

// paired mask test: elements idx, idx+1 with a single load
__device__ __forceinline__ void mask2_at(const void* m, int mode, size_t idx,
                                         bool& a, bool& b) {
    if (mode == 1) {
        unsigned short w = *(const unsigned short*)((const unsigned char*)m + idx);
        a = (w & 0xFFu) != 0; b = (w >> 8) != 0;
    } else if (mode == 0) {
        float2 v = *(const float2*)((const float*)m + idx);
        a = v.x != 0.0f; b = v.y != 0.0f;
    } else if (mode == 3) {
        unsigned w = *(const unsigned*)((const unsigned short*)m + idx);
        a = (w & 0xFFFFu) != 0; b = (w >> 16) != 0;
    } else {
        int2 v = *(const int2*)((const int*)m + idx);
        a = v.x != 0; b = v.y != 0;
    }
}

// ---------------------------------------------------------------------------
// Pack A[8192,1024] fp32 -> hi/lo fragment images (projection GEMM operand).
// ---------------------------------------------------------------------------
__global__ __launch_bounds__(256) void k_pack_a(
    const float* __restrict__ src,
    uint32_t* __restrict__ hi, uint32_t* __restrict__ lo)
{
    int idx = blockIdx.x * 256 + threadIdx.x;
    int r    = idx & 3;
    int lane = (idx >> 2) & 31;
    int ks   = (idx >> 7) & 63;
    int mblk = idx >> 13;
    int row = mblk * 16 + (lane >> 2) + (r & 1) * 8;
    int col = ks * 16 + (lane & 3) * 2 + (r >> 1) * 8;
    float2 x = *(const float2*)(src + (size_t)row * 1024 + col);
    uint32_t h, l;
    split_pair(x.x, x.y, h, l);
    hi[idx] = h; lo[idx] = l;
}

// ---------------------------------------------------------------------------
// Pack W[1024k,1024n] fp32 -> hi/lo B fragment images (col-major operand).
// ---------------------------------------------------------------------------
__global__ __launch_bounds__(256) void k_pack_w(
    const float* __restrict__ W,
    uint32_t* __restrict__ hi, uint32_t* __restrict__ lo)
{
    int idx = blockIdx.x * 256 + threadIdx.x;
    int r    = idx & 3;
    int lane = (idx >> 2) & 31;
    int ks   = (idx >> 7) & 63;
    int n16  = idx >> 13;
    int n = n16 * 16 + (r >> 1) * 8 + (lane >> 2);
    int k = ks * 16 + (lane & 3) * 2 + (r & 1) * 8;
    float x0 = W[(size_t)k * 1024 + n];
    float x1 = W[(size_t)(k + 1) * 1024 + n];
    uint32_t h, l;
    split_pair(x0, x1, h, l);
    hi[idx] = h; lo[idx] = l;
}

// V as B-operand: vp[bh][s][64], B[k=s][n=d] = vp[k][n] -> [bh][n16=4][ks64][lane][4]
__global__ __launch_bounds__(256) void k_pack_vb(
    const float* __restrict__ vp,
    uint32_t* __restrict__ hi, uint32_t* __restrict__ lo)
{
    int idx = blockIdx.x * 256 + threadIdx.x;
    int r    = idx & 3;
    int lane = (idx >> 2) & 31;
    int ks   = (idx >> 7) & 63;
    int n16  = (idx >> 13) & 3;
    int bh   = idx >> 15;
    int n = n16 * 16 + (r >> 1) * 8 + (lane >> 2);
    int k = ks * 16 + (lane & 3) * 2 + (r & 1) * 8;
    float x0 = vp[(((size_t)bh << 10) + k) * 64 + n];
    float x1 = vp[(((size_t)bh << 10) + k + 1) * 64 + n];
    uint32_t h, l;
    split_pair(x0, x1, h, l);
    hi[idx] = h; lo[idx] = l;
}

// ---------------------------------------------------------------------------
// Tensor-core split-bf16 GEMM: C[8192,1024] = A @ W (+bias, epilogue layout)
// MODE 0: head layout [b,h,s,64] with (acc+bias)*scale
// MODE 1: row-major [M,N] + bias
// MODE 2: emit K B-fragment images (khi/klo) directly, coalesced uint4 stores
// ---------------------------------------------------------------------------
template <int MODE>
__global__ __launch_bounds__(256) void k_mma_gemm(
    const uint4* __restrict__ Ahi, const uint4* __restrict__ Alo,
    const uint4* __restrict__ Bhi, const uint4* __restrict__ Blo,
    const float* __restrict__ bias, float scale, float* __restrict__ out,
    uint32_t* __restrict__ fhi, uint32_t* __restrict__ flo)
{
    const int tid = threadIdx.x, lane = tid & 31, wid = tid >> 5;
    const int warp_m = wid & 1, warp_n = wid >> 1;
    const int ntile = blockIdx.x, mtile = blockIdx.y;
    const int mb0 = mtile * 8 + warp_m * 4;
    const int nb0 = ntile * 8 + warp_n * 2;

    float acc[4][4][4];
#pragma unroll
    for (int i = 0; i < 4; i++)
#pragma unroll
        for (int j = 0; j < 4; j++)
#pragma unroll
            for (int c = 0; c < 4; c++) acc[i][j][c] = 0.f;

    uint4 ah[2][4], al[2][4], bh[2][2], bl[2][2];

#pragma unroll
    for (int i = 0; i < 4; i++) {
        ah[0][i] = Ahi[((size_t)(mb0 + i) * 64 + 0) * 32 + lane];
        al[0][i] = Alo[((size_t)(mb0 + i) * 64 + 0) * 32 + lane];
    }
#pragma unroll
    for (int j = 0; j < 2; j++) {
        bh[0][j] = Bhi[((size_t)(nb0 + j) * 64 + 0) * 32 + lane];
        bl[0][j] = Blo[((size_t)(nb0 + j) * 64 + 0) * 32 + lane];
    }

#pragma unroll 2
    for (int ks = 0; ks < 64; ks++) {
        const int cb = ks & 1, nb = cb ^ 1;
        if (ks + 1 < 64) {
#pragma unroll
            for (int i = 0; i < 4; i++) {
                ah[nb][i] = Ahi[((size_t)(mb0 + i) * 64 + ks + 1) * 32 + lane];
                al[nb][i] = Alo[((size_t)(mb0 + i) * 64 + ks + 1) * 32 + lane];
            }
#pragma unroll
            for (int j = 0; j < 2; j++) {
                bh[nb][j] = Bhi[((size_t)(nb0 + j) * 64 + ks + 1) * 32 + lane];
                bl[nb][j] = Blo[((size_t)(nb0 + j) * 64 + ks + 1) * 32 + lane];
            }
        }
#pragma unroll
        for (int i = 0; i < 4; i++) {
            const uint4 A = ah[cb][i], L = al[cb][i];
#pragma unroll
            for (int j = 0; j < 2; j++) {
                const uint4 Bh = bh[cb][j], Bl = bl[cb][j];
                mma_bf16(acc[i][j * 2], A.x, A.y, A.z, A.w, Bh.x, Bh.y);
                mma_bf16(acc[i][j * 2], L.x, L.y, L.z, L.w, Bh.x, Bh.y);
                mma_bf16(acc[i][j * 2], A.x, A.y, A.z, A.w, Bl.x, Bl.y);
                mma_bf16(acc[i][j * 2 + 1], A.x, A.y, A.z, A.w, Bh.z, Bh.w);
                mma_bf16(acc[i][j * 2 + 1], L.x, L.y, L.z, L.w, Bh.z, Bh.w);
                mma_bf16(acc[i][j * 2 + 1], A.x, A.y, A.z, A.w, Bl.z, Bl.w);
            }
        }
    }

    if (MODE == 2) {
        // Emit K B-fragment image: pairs along dk; r = (j&1) + 2*half.
        // Words (r=0..3) for fixed (i, jpair) are contiguous -> one uint4.
#pragma unroll
        for (int i = 0; i < 4; i++) {
            const int row = mtile * 128 + warp_m * 64 + i * 16 + (lane >> 2);
            const int bb = row >> 10;
            const int n16 = (row >> 4) & 63;
#pragma unroll
            for (int jp = 0; jp < 2; jp++) {
                const int colb = ntile * 128 + warp_n * 32 + jp * 16 + (lane & 3) * 2;
                const int hh = colb >> 6;
                const int ks2 = (colb & 63) >> 4;
                uint32_t hw[4], lw[4];
#pragma unroll
                for (int half = 0; half < 2; half++) {
#pragma unroll
                    for (int jj = 0; jj < 2; jj++) {
                        const int j = jp * 2 + jj;
                        const int c = ntile * 128 + warp_n * 32 + j * 8 + (lane & 3) * 2;
                        float v0 = acc[i][j][half * 2 + 0] + bias[c];
                        float v1 = acc[i][j][half * 2 + 1] + bias[c + 1];
                        split_pair(v0, v1, hw[jj + half * 2], lw[jj + half * 2]);
                    }
                }
                size_t widx =
                    ((((size_t)((bb * 16 + hh) * 64 + n16)) * 4 + ks2) * 32 + lane) * 4;
                *(uint4*)&fhi[widx] = make_uint4(hw[0], hw[1], hw[2], hw[3]);
                *(uint4*)&flo[widx] = make_uint4(lw[0], lw[1], lw[2], lw[3]);
            }
        }
        return;
    }

#pragma unroll
    for (int i = 0; i < 4; i++) {
        const int row0 = mtile * 128 + warp_m * 64 + i * 16 + (lane >> 2);
#pragma unroll
        for (int j = 0; j < 4; j++) {
            const int col0 = ntile * 128 + warp_n * 32 + j * 8 + (lane & 3) * 2;
            const float b0 = bias[col0], b1 = bias[col0 + 1];
#pragma unroll
            for (int half = 0; half < 2; half++) {
                const int row = row0 + half * 8;
                float v0 = acc[i][j][half * 2 + 0] + b0;
                float v1 = acc[i][j][half * 2 + 1] + b1;
                if (MODE == 0) {
                    v0 *= scale; v1 *= scale;
                    const int bb = row >> 10, ss = row & 1023;
                    const int hh = col0 >> 6, dk = col0 & 63;
                    float* dst = out + ((((size_t)(bb * 16 + hh)) << 10) + ss) * 64 + dk;
                    *(float2*)dst = make_float2(v0, v1);
                } else {
                    *(float2*)(out + (size_t)row * 1024 + col0) = make_float2(v0, v1);
                }
            }
        }
    }
}

// ---------------------------------------------------------------------------
// qrel[bhs][t] = sum_d qp[bhs][d] * rel_k[t][d]   (q already scaled)
// ---------------------------------------------------------------------------
__global__ __launch_bounds__(256) void k_qrel(const float* __restrict__ qp,
                                              const float* __restrict__ rel_k,
                                              float* __restrict__ qrel)
{
    __shared__ float rk[V_ * 65];
    __shared__ float qs[8 * DK_];
    const int tid = threadIdx.x;
    const long long r0 = (long long)blockIdx.x * 8;
    for (int i = tid; i < V_ * DK_; i += 256) {
        int t = i / DK_, d = i % DK_;
        rk[t * 65 + d] = rel_k[i];
    }
    for (int i = tid; i < 8 * DK_; i += 256) qs[i] = qp[r0 * DK_ + i];
    __syncthreads();
    const int wr = tid >> 5, lane = tid & 31;
    for (int t = lane; t < V_; t += 32) {
        float s = 0.f;
#pragma unroll
        for (int d = 0; d < DK_; d++) s += qs[wr * DK_ + d] * rk[t * 65 + d];
        qrel[(r0 + wr) * V_ + t] = s;
    }
}

// fold helper: -log(adj) with adj in {1,2} fast paths
__device__ __forceinline__ float adj_fold(float av) {
    if (av == 1.0f) return 0.f;
    if (av == 2.0f) return 0.69314718055994530942f;
    return __logf(av);
}

// ---------------------------------------------------------------------------
// Pass A: QK mma + fold + scores store + online softmax row stats.
// grid (8 qtiles, 128 bh), 256 thr; warp = 16 q rows x all 1024 k.
// ---------------------------------------------------------------------------
__global__ __launch_bounds__(256) void k_qk_stats(
    const float* __restrict__ qp,
    const uint4* __restrict__ Khi, const uint4* __restrict__ Klo,
    const float* __restrict__ qrel, const void* __restrict__ mask,
    const float* __restrict__ adj, float* __restrict__ scores,
    float2* __restrict__ stats)
{
    const int tid = threadIdx.x, lane = tid & 31, wid = tid >> 5;
    const int qtile = blockIdx.x, bh = blockIdx.y;
    const int row0 = qtile * 128 + wid * 16 + (lane >> 2);
    const int row1 = row0 + 8;
    const size_t qbase = ((size_t)bh << 10);

    // Q fragments directly from qp (split on the fly, reused for all k)
    uint32_t qh[4][4], ql[4][4];
#pragma unroll
    for (int ks = 0; ks < 4; ks++) {
        const int c0 = ks * 16 + (lane & 3) * 2;
        float2 x0 = *(const float2*)(qp + (qbase + row0) * 64 + c0);
        float2 x1 = *(const float2*)(qp + (qbase + row1) * 64 + c0);
        float2 x2 = *(const float2*)(qp + (qbase + row0) * 64 + c0 + 8);
        float2 x3 = *(const float2*)(qp + (qbase + row1) * 64 + c0 + 8);
        split_pair(x0.x, x0.y, qh[ks][0], ql[ks][0]);
        split_pair(x1.x, x1.y, qh[ks][1], ql[ks][1]);
        split_pair(x2.x, x2.y, qh[ks][2], ql[ks][2]);
        split_pair(x3.x, x3.y, qh[ks][3], ql[ks][3]);
    }

    const int mode = g_mask_mode;
    const int bb = bh >> 4;
    const float* qr0 = qrel + (qbase + row0) * V_;
    const float* qr1 = qrel + (qbase + row1) * V_;
    const float qlo0 = qr0[0], qhi0 = qr0[64];
    const float qlo1 = qr1[0], qhi1 = qr1[64];
    const size_t arow0 = (qbase + row0) << 10;
    const size_t arow1 = (qbase + row1) << 10;
    const size_t mrow0 = (((size_t)bb << 10) + row0) << 10;
    const size_t mrow1 = (((size_t)bb << 10) + row1) << 10;
    const size_t kb = (size_t)bh * 8192;   // uint4 per head K image

    float m0 = -3.4e38f, m1 = -3.4e38f, s0 = 0.f, s1 = 0.f;

    for (int kt = 0; kt < 16; kt++) {      // 64-col tiles
        float acc[8][4];
#pragma unroll
        for (int p = 0; p < 8; p++)
#pragma unroll
            for (int c = 0; c < 4; c++) acc[p][c] = 0.f;

#pragma unroll
        for (int ks = 0; ks < 4; ks++) {
#pragma unroll
            for (int b = 0; b < 4; b++) {
                const int n16 = kt * 4 + b;
                const uint4 Bh = Khi[kb + (size_t)(n16 * 4 + ks) * 32 + lane];
                const uint4 Bl = Klo[kb + (size_t)(n16 * 4 + ks) * 32 + lane];
                mma_bf16(acc[b*2],   qh[ks][0], qh[ks][1], qh[ks][2], qh[ks][3], Bh.x, Bh.y);
                mma_bf16(acc[b*2],   ql[ks][0], ql[ks][1], ql[ks][2], ql[ks][3], Bh.x, Bh.y);
                mma_bf16(acc[b*2],   qh[ks][0], qh[ks][1], qh[ks][2], qh[ks][3], Bl.x, Bl.y);
                mma_bf16(acc[b*2+1], qh[ks][0], qh[ks][1], qh[ks][2], qh[ks][3], Bh.z, Bh.w);
                mma_bf16(acc[b*2+1], ql[ks][0], ql[ks][1], ql[ks][2], ql[ks][3], Bh.z, Bh.w);
                mma_bf16(acc[b*2+1], qh[ks][0], qh[ks][1], qh[ks][2], qh[ks][3], Bl.z, Bl.w);
            }
        }

        // tile-level relative-position classification (band is |k-q|<32)
        const int tlo = kt * 64;
        const bool pre0a = (tlo + 63 <= row0 - 32);
        const bool suf0a = (tlo >= row0 + 32);
        const bool pre1a = (tlo + 63 <= row1 - 32);
        const bool suf1a = (tlo >= row1 + 32);

        float tm0 = -3.4e38f, tm1 = -3.4e38f;
#pragma unroll
        for (int p = 0; p < 8; p++) {
            const int col = tlo + p * 8 + (lane & 3) * 2;
            // row0 pair
            {
                float r0x, r0y;
                if (pre0a)      { r0x = qlo0; r0y = qlo0; }
                else if (suf0a) { r0x = qhi0; r0y = qhi0; }
                else {
                    int d0 = col - row0;     d0 = d0 < -32 ? -32 : (d0 > 32 ? 32 : d0);
                    int d1 = col + 1 - row0; d1 = d1 < -32 ? -32 : (d1 > 32 ? 32 : d1);
                    r0x = qr0[d0 + 32]; r0y = qr0[d1 + 32];
                }
                float v0 = acc[p][0] + r0x;
                float v1 = acc[p][1] + r0y;
                float2 av = *(const float2*)(adj + arow0 + col);
                bool ma, mb;
                mask2_at(mask, mode, mrow0 + col, ma, mb);
                if (ma || av.x == 0.0f) v0 = -1e30f; else v0 -= adj_fold(av.x);
                if (mb || av.y == 0.0f) v1 = -1e30f; else v1 -= adj_fold(av.y);
                *(float2*)(scores + arow0 + col) = make_float2(v0, v1);
                tm0 = fmaxf(tm0, fmaxf(v0, v1));
                acc[p][0] = v0; acc[p][1] = v1;
            }
            // row1 pair
            {
                float r1x, r1y;
                if (pre1a)      { r1x = qlo1; r1y = qlo1; }
                else if (suf1a) { r1x = qhi1; r1y = qhi1; }
                else {
                    int d0 = col - row1;     d0 = d0 < -32 ? -32 : (d0 > 32 ? 32 : d0);
                    int d1 = col + 1 - row1; d1 = d1 < -32 ? -32 : (d1 > 32 ? 32 : d1);
                    r1x = qr1[d0 + 32]; r1y = qr1[d1 + 32];
                }
                float v0 = acc[p][2] + r1x;
                float v1 = acc[p][3] + r1y;
                float2 av = *(const float2*)(adj + arow1 + col);
                bool ma, mb;
                mask2_at(mask, mode, mrow1 + col, ma, mb);
                if (ma || av.x == 0.0f) v0 = -1e30f; else v0 -= adj_fold(av.x);
                if (mb || av.y == 0.0f) v1 = -1e30f; else v1 -= adj_fold(av.y);
                *(float2*)(scores + arow1 + col) = make_float2(v0, v1);
                tm1 = fmaxf(tm1, fmaxf(v0, v1));
                acc[p][2] = v0; acc[p][3] = v1;
            }
        }
        // online (max, sum) update
        const float nm0 = fmaxf(m0, tm0);
        const float nm1 = fmaxf(m1, tm1);
        s0 *= __expf(m0 - nm0);
        s1 *= __expf(m1 - nm1);
#pragma unroll
        for (int p = 0; p < 8; p++) {
            s0 += __expf(acc[p][0] - nm0) + __expf(acc[p][1] - nm0);
            s1 += __expf(acc[p][2] - nm1) + __expf(acc[p][3] - nm1);
        }
        m0 = nm0; m1 = nm1;
    }

    // combine across the 4 lanes sharing each row
#pragma unroll
    for (int o = 1; o <= 2; o <<= 1) {
        float om = __shfl_xor_sync(0xffffffffu, m0, o);
        float os = __shfl_xor_sync(0xffffffffu, s0, o);
        float nm = fmaxf(m0, om);
        s0 = s0 * __expf(m0 - nm) + os * __expf(om - nm); m0 = nm;
        om = __shfl_xor_sync(0xffffffffu, m1, o);
        os = __shfl_xor_sync(0xffffffffu, s1, o);
        nm = fmaxf(m1, om);
        s1 = s1 * __expf(m1 - nm) + os * __expf(om - nm); m1 = nm;
    }
    if ((lane & 3) == 0) {
        stats[qbase + row0] = make_float2(m0, s0);
        stats[qbase + row1] = make_float2(m1, s1);
    }
}

// ---------------------------------------------------------------------------
// Pass B: read scores, p = exp(s-mx)*inv, write attn to d_out, rel-value
// buckets, and AV via mma with p repacked in-register as A fragments.
// grid (8 qtiles, 128 bh), 256 thr; warp = 16 q rows.
// ---------------------------------------------------------------------------
__global__ __launch_bounds__(256) void k_av_fused(
    const float* __restrict__ scores,
    const uint4* __restrict__ Vhi, const uint4* __restrict__ Vlo,
    const float2* __restrict__ stats, float* __restrict__ wbuf,
    float* __restrict__ attn_out, float* __restrict__ ctx)
{
    const int tid = threadIdx.x, lane = tid & 31, wid = tid >> 5;
    const int qtile = blockIdx.x, bh = blockIdx.y;
    const int row0 = qtile * 128 + wid * 16 + (lane >> 2);
    const int row1 = row0 + 8;
    const size_t grow0 = ((size_t)bh << 10) + row0;

    const float2 st0 = stats[grow0];
    const float2 st1 = stats[grow0 + 8];
    const float mx0 = st0.x, inv0 = st0.y > 0.f ? 1.f / st0.y : 0.f;
    const float mx1 = st1.x, inv1 = st1.y > 0.f ? 1.f / st1.y : 0.f;

    // zero this warp's 16 wbuf rows
    const size_t wrbase = ((size_t)bh << 10) + qtile * 128 + wid * 16;
    for (int i = lane; i < 16 * V_; i += 32) wbuf[wrbase * V_ + i] = 0.f;
    __syncwarp();

    float cacc[4][2][4];
#pragma unroll
    for (int nb = 0; nb < 4; nb++)
#pragma unroll
        for (int e = 0; e < 2; e++)
#pragma unroll
            for (int c = 0; c < 4; c++) cacc[nb][e][c] = 0.f;

    float pre0 = 0.f, suf0 = 0.f, pre1 = 0.f, suf1 = 0.f;
    const float* s0p = scores + (grow0 << 10);
    const float* s1p = s0p + (size_t)8 * 1024;
    float* a0p = attn_out ? attn_out + (grow0 << 10) : nullptr;
    float* wr0 = wbuf + grow0 * V_;
    float* wr1 = wr0 + (size_t)8 * V_;
    const size_t vb = (size_t)bh * 8192;

#pragma unroll 2
    for (int kstep = 0; kstep < 64; kstep++) {
        const int col = kstep * 16 + (lane & 3) * 2;
        float2 v00 = *(const float2*)(s0p + col);
        float2 v01 = *(const float2*)(s0p + col + 8);
        float2 v10 = *(const float2*)(s1p + col);
        float2 v11 = *(const float2*)(s1p + col + 8);
        v00.x = __expf(v00.x - mx0) * inv0; v00.y = __expf(v00.y - mx0) * inv0;
        v01.x = __expf(v01.x - mx0) * inv0; v01.y = __expf(v01.y - mx0) * inv0;
        v10.x = __expf(v10.x - mx1) * inv1; v10.y = __expf(v10.y - mx1) * inv1;
        v11.x = __expf(v11.x - mx1) * inv1; v11.y = __expf(v11.y - mx1) * inv1;
        if (a0p) {
            *(float2*)(a0p + col)              = v00;
            *(float2*)(a0p + col + 8)          = v01;
            *(float2*)(a0p + 8 * 1024 + col)     = v10;
            *(float2*)(a0p + 8 * 1024 + col + 8) = v11;
        }
        // rel-value buckets, tile-classified (tile = 16 cols)
        {
            const int tlo = kstep * 16;
            const float sum0 = v00.x + v00.y + v01.x + v01.y;
            const float sum1 = v10.x + v10.y + v11.x + v11.y;
            if (tlo + 15 <= row0 - 32)      pre0 += sum0;
            else if (tlo >= row0 + 32)      suf0 += sum0;
            else {
                float pv[4] = {v00.x, v00.y, v01.x, v01.y};
                int   kc[4] = {col, col + 1, col + 8, col + 9};
#pragma unroll
                for (int e = 0; e < 4; e++) {
                    int d = kc[e] - row0;
                    if (d <= -32)      pre0 += pv[e];
                    else if (d >= 32)  suf0 += pv[e];
                    else               wr0[d + 32] = pv[e];
                }
            }
            if (tlo + 15 <= row1 - 32)      pre1 += sum1;
            else if (tlo >= row1 + 32)      suf1 += sum1;
            else {
                float qv[4] = {v10.x, v10.y, v11.x, v11.y};
                int   kc[4] = {col, col + 1, col + 8, col + 9};
#pragma unroll
                for (int e = 0; e < 4; e++) {
                    int d = kc[e] - row1;
                    if (d <= -32)      pre1 += qv[e];
                    else if (d >= 32)  suf1 += qv[e];
                    else               wr1[d + 32] = qv[e];
                }
            }
        }
        // repack p as A fragments (QK acc layout == AV A-frag layout)
        uint32_t ah0, ah1, ah2, ah3, al0, al1, al2, al3;
        split_pair(v00.x, v00.y, ah0, al0);
        split_pair(v10.x, v10.y, ah1, al1);
        split_pair(v01.x, v01.y, ah2, al2);
        split_pair(v11.x, v11.y, ah3, al3);
#pragma unroll
        for (int nb = 0; nb < 4; nb++) {
            const uint4 Bh = Vhi[vb + (size_t)(nb * 64 + kstep) * 32 + lane];
            const uint4 Bl = Vlo[vb + (size_t)(nb * 64 + kstep) * 32 + lane];
            mma_bf16(cacc[nb][0], ah0, ah1, ah2, ah3, Bh.x, Bh.y);
            mma_bf16(cacc[nb][0], al0, al1, al2, al3, Bh.x, Bh.y);
            mma_bf16(cacc[nb][0], ah0, ah1, ah2, ah3, Bl.x, Bl.y);
            mma_bf16(cacc[nb][1], ah0, ah1, ah2, ah3, Bh.z, Bh.w);
            mma_bf16(cacc[nb][1], al0, al1, al2, al3, Bh.z, Bh.w);
            mma_bf16(cacc[nb][1], ah0, ah1, ah2, ah3, Bl.z, Bl.w);
        }
    }

    // reduce pre/suf across the 4 lanes per row, write bucket endpoints
#pragma unroll
    for (int o = 1; o <= 2; o <<= 1) {
        pre0 += __shfl_xor_sync(0xffffffffu, pre0, o);
        suf0 += __shfl_xor_sync(0xffffffffu, suf0, o);
        pre1 += __shfl_xor_sync(0xffffffffu, pre1, o);
        suf1 += __shfl_xor_sync(0xffffffffu, suf1, o);
    }
    if ((lane & 3) == 0) {
        wr0[0] = pre0; wr0[64] = suf0;
        wr1[0] = pre1; wr1[64] = suf1;
    }

    // ctx write [b][s][h*64+d]
    const int bb = bh >> 4, hh = bh & 15;
#pragma unroll
    for (int nb = 0; nb < 4; nb++)
#pragma unroll
        for (int e = 0; e < 2; e++) {
            const int d = nb * 16 + e * 8 + (lane & 3) * 2;
#pragma unroll
            for (int half = 0; half < 2; half++) {
                const int q = row0 + half * 8;
                float2 v = make_float2(cacc[nb][e][half * 2 + 0],
                                       cacc[nb][e][half * 2 + 1]);
                *(float2*)(ctx + (((size_t)bb << 10) + q) * 1024 + hh * 64 + d) = v;
            }
        }
}

// ---------------------------------------------------------------------------
// ctx += w @ rel_v   (65x64 per row)
// ---------------------------------------------------------------------------
__global__ __launch_bounds__(256) void k_relctx(const float* __restrict__ wbuf,
                                                const float* __restrict__ rel_v,
                                                float* __restrict__ ctx)
{
    __shared__ float rv[V_ * 64];
    __shared__ float ws[4][V_];
    const int tid = threadIdx.x;
    const long long r0 = (long long)blockIdx.x * 4;
    for (int i = tid; i < V_ * 64; i += 256) rv[i] = rel_v[i];
    for (int i = tid; i < 4 * V_; i += 256)
        ws[i / V_][i % V_] = wbuf[(r0 + i / V_) * V_ + i % V_];
    __syncthreads();
    const int rr = tid >> 6;
    const int d = tid & 63;
    float acc = 0.f;
#pragma unroll
    for (int t = 0; t < V_; t++) acc += ws[rr][t] * rv[t * 64 + d];
    long long r = r0 + rr;
    int bh = (int)(r >> 10), s = (int)(r & 1023);
    int bb = bh >> 4, hh = bh & 15;
    ctx[((size_t)(bb * S_ + s)) * D_ + hh * 64 + d] += acc;
}

// ---------------------------------------------------------------------------
// Launch
// ---------------------------------------------------------------------------
extern "C" void kernel_launch(void* const* d_in, const int* in_sizes, int n_in,
                              void* d_out, int out_size)
{
    const float* key   = (const float*)d_in[0];
    const float* value = (const float*)d_in[1];
    const float* query = (const float*)d_in[2];
    const void*  mask  = d_in[3];
    const float* adj   = (const float*)d_in[4];
    const float* Wq = (const float*)d_in[5];
    const float* bq = (const float*)d_in[6];
    const float* Wk = (const float*)d_in[7];
    const float* bk = (const float*)d_in[8];
    const float* Wv = (const float*)d_in[9];
    const float* bv = (const float*)d_in[10];
    const float* Wo = (const float*)d_in[11];
    const float* bo = (const float*)d_in[12];
    const float* rel_k = (const float*)d_in[13];
    const float* rel_v = (const float*)d_in[14];
    float* outF = (float*)d_out;

    float *qp, *vp, *qrel, *wb, *sc, *ctx;
    float2* stats;
    uint32_t *ahi, *alo, *whi, *wlo, *khi, *klo, *vhi, *vlo;
    cudaGetSymbolAddress((void**)&qp,    g_qp);
    cudaGetSymbolAddress((void**)&vp,    g_vp);
    cudaGetSymbolAddress((void**)&qrel,  g_qrel);
    cudaGetSymbolAddress((void**)&wb,    g_w);
    cudaGetSymbolAddress((void**)&sc,    g_scores);
    cudaGetSymbolAddress((void**)&ctx,   g_ctx);
    cudaGetSymbolAddress((void**)&stats, g_stats);
    cudaGetSymbolAddress((void**)&ahi,   g_Ahi);
    cudaGetSymbolAddress((void**)&alo,   g_Alo);
    cudaGetSymbolAddress((void**)&whi,   g_Whi);
    cudaGetSymbolAddress((void**)&wlo,   g_Wlo);
    cudaGetSymbolAddress((void**)&khi,   g_Khi);
    cudaGetSymbolAddress((void**)&klo,   g_Klo);
    cudaGetSymbolAddress((void**)&vhi,   g_Vhi);
    cudaGetSymbolAddress((void**)&vlo,   g_Vlo);

    // mask dtype detection
    k_reset_flags<<<1, 1>>>();
    k_detect_mask<<<256, 256>>>((const unsigned*)mask, in_sizes[3] / 4);
    k_finalize_mask<<<1, 1>>>();

    const int APACK_BLOCKS = MROWS * D_ / 2 / 256;   // 16384
    const int WPACK_BLOCKS = D_ * D_ / 2 / 256;      // 2048
    const int HPACK_BLOCKS = HEADW / 256;            // 16384
    dim3 gg(8, 64);   // (ntiles, mtiles)

    // Q projection (pre-scaled by 1/8 incl. bias)
    k_pack_w<<<WPACK_BLOCKS, 256>>>(Wq, whi, wlo);
    k_pack_a<<<APACK_BLOCKS, 256>>>(query, ahi, alo);
    k_mma_gemm<0><<<gg, 256>>>((const uint4*)ahi, (const uint4*)alo,
                               (const uint4*)whi, (const uint4*)wlo, bq, 0.125f, qp,
                               nullptr, nullptr);

    // K projection — emits K B-fragment images directly (no kp, no pack_kb)
    k_pack_w<<<WPACK_BLOCKS, 256>>>(Wk, whi, wlo);
    k_pack_a<<<APACK_BLOCKS, 256>>>(key, ahi, alo);
    k_mma_gemm<2><<<gg, 256>>>((const uint4*)ahi, (const uint4*)alo,
                               (const uint4*)whi, (const uint4*)wlo, bk, 1.0f, nullptr,
                               khi, klo);

    // V projection
    k_pack_w<<<WPACK_BLOCKS, 256>>>(Wv, whi, wlo);
    k_pack_a<<<APACK_BLOCKS, 256>>>(value, ahi, alo);
    k_mma_gemm<0><<<gg, 256>>>((const uint4*)ahi, (const uint4*)alo,
                               (const uint4*)whi, (const uint4*)wlo, bv, 1.0f, vp,
                               nullptr, nullptr);

    // V B-fragment pack
    k_pack_vb<<<HPACK_BLOCKS, 256>>>(vp, vhi, vlo);

    // relative-key projection (rank-65 trick)
    k_qrel<<<NROW / 8, 256>>>(qp, rel_k, qrel);

    // Pass A: scores + fold + row stats
    dim3 ag(8, BH_);
    k_qk_stats<<<ag, 256>>>(qp, (const uint4*)khi, (const uint4*)klo,
                            qrel, mask, adj, sc, stats);

    // Pass B: normalize + attn out + buckets + AV
    bool hasAttn = (size_t)out_size >= (size_t)FINAL_ELEMS + SCORES_ELEMS;
    float* attnOut = hasAttn ? outF + FINAL_ELEMS : nullptr;
    k_av_fused<<<ag, 256>>>(sc, (const uint4*)vhi, (const uint4*)vlo,
                            stats, wb, attnOut, ctx);

    k_relctx<<<NROW / 4, 256>>>(wb, rel_v, ctx);

    // output projection (row-major epilogue)
    k_pack_w<<<WPACK_BLOCKS, 256>>>(Wo, whi, wlo);
    k_pack_a<<<APACK_BLOCKS, 256>>>(ctx, ahi, alo);
    k_mma_gemm<1><<<gg, 256>>>((const uint4*)ahi, (const uint4*)alo,
                               (const uint4*)whi, (const uint4*)wlo, bo, 1.0f, outF,
                               nullptr, nullptr);
}